// round 13
// baseline (speedup 1.0000x reference)
#include <cuda_runtime.h>
#include <cuda_fp16.h>
#include <cstdint>

// Problem constants (fixed by the dataset)
#define NN 100000
#define EE 1600000
#define SCAN_B 1024
#define MAX_BLOCKS 128   // ceil(NN/1024) = 98 <= 128

// Scratch (no cudaMalloc allowed)
__device__ int   g_deg[NN];
__device__ __align__(16) float g_dinv[NN];
__device__ int   g_start[NN + 1];
__device__ int   g_cursor[NN];
__device__ int   g_bsums[MAX_BLOCKS];
__device__ __align__(16) int2   g_ew[EE];                   // packed {srcrow, w bits}
__device__ __align__(16) __half g_x16[(size_t)NN * 128];    // fp16 copy of input x
__device__ __align__(16) __half g_h[(size_t)NN * 128];      // GEMM output (fp16)
__device__ __align__(16) __half g_act[(size_t)NN * 128];    // inter-layer activations (fp16)
__device__ __align__(16) __half g_w1t[128 * 128];           // W1 fp16 row-major
__device__ __align__(16) __half g_w2t[128 * 128];           // W2 fp16
__device__ __align__(16) __half g_w3t[128 * 64];            // W3 fp16

// ---------------- prologue ----------------

__global__ void zero_deg_k(int* __restrict__ p, int n) {
    int i = blockIdx.x * blockDim.x + threadIdx.x;
    if (i < n) p[i] = 0;
}

__global__ void cvt16_k(const float4* __restrict__ x, uint2* __restrict__ x16, int n4) {
    int i = blockIdx.x * blockDim.x + threadIdx.x;
    if (i < n4) {
        float4 f = __ldg(x + i);
        half2 a = __floats2half2_rn(f.x, f.y);
        half2 b = __floats2half2_rn(f.z, f.w);
        uint2 o;
        o.x = *(const uint32_t*)&a;
        o.y = *(const uint32_t*)&b;
        x16[i] = o;
    }
}

__global__ void wprep_k(const float* __restrict__ W, __half* __restrict__ Wt, int total) {
    int i = blockIdx.x * blockDim.x + threadIdx.x;
    if (i < total) Wt[i] = __float2half_rn(W[i]);
}

__global__ void degree_k(const int* __restrict__ col, int* __restrict__ deg, int E) {
    int e = blockIdx.x * blockDim.x + threadIdx.x;
    if (e < E) atomicAdd(&deg[col[e]], 1);
}

__global__ void scan1_dinv_k(const int* __restrict__ deg, int* __restrict__ start,
                             int* __restrict__ bsums, float* __restrict__ dinv, int n) {
    __shared__ int s[SCAN_B];
    int i = blockIdx.x * SCAN_B + threadIdx.x;
    int v = (i < n) ? deg[i] : 0;
    if (i < n) dinv[i] = (v > 0) ? rsqrtf((float)v) : 0.0f;
    s[threadIdx.x] = v;
    __syncthreads();
    for (int off = 1; off < SCAN_B; off <<= 1) {
        int t = (threadIdx.x >= off) ? s[threadIdx.x - off] : 0;
        __syncthreads();
        s[threadIdx.x] += t;
        __syncthreads();
    }
    if (i < n) start[i + 1] = s[threadIdx.x];
    if (threadIdx.x == SCAN_B - 1) bsums[blockIdx.x] = s[SCAN_B - 1];
}

__global__ void scan2_k(int* __restrict__ bsums, int nb) {
    __shared__ int s[MAX_BLOCKS];
    int v = (threadIdx.x < nb) ? bsums[threadIdx.x] : 0;
    s[threadIdx.x] = v;
    __syncthreads();
    for (int off = 1; off < MAX_BLOCKS; off <<= 1) {
        int t = (threadIdx.x >= off) ? s[threadIdx.x - off] : 0;
        __syncthreads();
        s[threadIdx.x] += t;
        __syncthreads();
    }
    if (threadIdx.x < nb) bsums[threadIdx.x] = s[threadIdx.x] - v;  // exclusive
}

__global__ void scan3_cursor_k(int* __restrict__ start, const int* __restrict__ bsums,
                               int* __restrict__ cursor, int n) {
    int i = blockIdx.x * blockDim.x + threadIdx.x;
    if (i < n) {
        int v = start[i + 1] + bsums[i >> 10];
        start[i + 1] = v;
        if (i + 1 < n) cursor[i + 1] = v;
        if (i == 0) { start[0] = 0; cursor[0] = 0; }
    }
}

__global__ void fill_k(const int* __restrict__ row, const int* __restrict__ col,
                       const float* __restrict__ dinv, int* __restrict__ cursor,
                       int2* __restrict__ ew, int E) {
    int e = blockIdx.x * blockDim.x + threadIdx.x;
    if (e < E) {
        int r = row[e];
        int c = col[e];
        int pos = atomicAdd(&cursor[c], 1);
        ew[pos] = make_int2(r, __float_as_int(dinv[r] * dinv[c]));
    }
}

// ---------------- tensor-core GEMM (mma.sync), persistent + double-buffered ----
// H[n,FOUT] = fp16( X16[n,128] @ W16[128,FOUT] ), fp32 accumulate.
// Grid-stride over TM-row tiles; W loaded once per block; X tiles double-buffered
// via cp.async so copies overlap the previous tile's mainloop.

__device__ __forceinline__ uint32_t smem_u32(const void* p) {
    uint32_t a;
    asm("{ .reg .u64 t; cvta.to.shared.u64 t, %1; cvt.u32.u64 %0, t; }" : "=r"(a) : "l"(p));
    return a;
}

__device__ __forceinline__ void cp_async16(uint32_t dst, const void* src, uint32_t sz) {
    asm volatile("cp.async.cg.shared.global [%0], [%1], 16, %2;"
                 :: "r"(dst), "l"(src), "r"(sz) : "memory");
}

__device__ __forceinline__ void cp_async_commit() {
    asm volatile("cp.async.commit_group;" ::: "memory");
}
__device__ __forceinline__ void cp_async_wait0() {
    asm volatile("cp.async.wait_group 0;" ::: "memory");
}

__device__ __forceinline__ void mma16816(float* c,
    uint32_t a0, uint32_t a1, uint32_t a2, uint32_t a3,
    uint32_t b0, uint32_t b1) {
    asm volatile(
        "mma.sync.aligned.m16n8k16.row.col.f32.f16.f16.f32 "
        "{%0,%1,%2,%3}, {%4,%5,%6,%7}, {%8,%9}, {%0,%1,%2,%3};"
        : "+f"(c[0]), "+f"(c[1]), "+f"(c[2]), "+f"(c[3])
        : "r"(a0), "r"(a1), "r"(a2), "r"(a3), "r"(b0), "r"(b1));
}

__device__ __forceinline__ void ldsm_x4(uint32_t addr, uint32_t& r0, uint32_t& r1,
                                        uint32_t& r2, uint32_t& r3) {
    asm volatile("ldmatrix.sync.aligned.m8n8.x4.shared.b16 {%0,%1,%2,%3}, [%4];"
                 : "=r"(r0), "=r"(r1), "=r"(r2), "=r"(r3) : "r"(addr));
}

__device__ __forceinline__ void ldsm_x4_t(uint32_t addr, uint32_t& r0, uint32_t& r1,
                                          uint32_t& r2, uint32_t& r3) {
    asm volatile("ldmatrix.sync.aligned.m8n8.x4.trans.shared.b16 {%0,%1,%2,%3}, [%4];"
                 : "=r"(r0), "=r"(r1), "=r"(r2), "=r"(r3) : "r"(addr));
}

#define XP 136
#define WP 136

template <int FOUT>
__global__ __launch_bounds__(256, 2)
void gemm_k(const __half* __restrict__ X, const __half* __restrict__ Wt,
            __half* __restrict__ H, int n, int ntiles) {
    constexpr int TM = (FOUT == 128) ? 64 : 128;  // rows per tile
    constexpr int NW = FOUT / 64;                 // warps along N (2 or 1)

    extern __shared__ __half smh[];
    __half* Xb[2] = { smh, smh + TM * XP };
    __half* Wsm = smh + 2 * TM * XP;     // 128 x WP, row-major [k][c]

    const int tid  = threadIdx.x;
    const int warp = tid >> 5;
    const int lane = tid & 31;
    const int g = lane >> 2;
    const int t4 = lane & 3;

    const uint32_t xb_u32[2] = { smem_u32(Xb[0]), smem_u32(Xb[1]) };
    const uint32_t wm_u32 = smem_u32(Wsm);

    // W fill (once per block)
    for (int u = tid; u < 128 * (FOUT / 8); u += 256) {
        int k = u / (FOUT / 8), c8 = (u % (FOUT / 8)) * 8;
        cp_async16(wm_u32 + (k * WP + c8) * 2, Wt + k * FOUT + c8, 16u);
    }

    // X tile fill helper
    auto fillX = [&](uint32_t xdst, int tt) {
        int row0 = tt * TM;
        for (int u = tid; u < TM * 16; u += 256) {
            int r = u >> 4, m = u & 15;
            bool ok = (row0 + r < n);
            const __half* src = X + (size_t)(ok ? (row0 + r) : 0) * 128 + m * 8;
            cp_async16(xdst + (r * XP + m * 8) * 2, src, ok ? 16u : 0u);
        }
    };

    int t = blockIdx.x;
    if (t >= ntiles) return;
    fillX(xb_u32[0], t);
    cp_async_commit();
    cp_async_wait0();
    __syncthreads();

    const int wm = (warp / NW) * 16;      // warp row base within tile
    const int n0 = (warp % NW) * 64;      // warp col base
    const int lrow = lane & 15;
    const int lk8  = ((lane >> 4) & 1) * 8;
    const uint32_t wb_base = wm_u32 + (lrow * WP + n0 + lk8) * 2;

    int buf = 0;
    for (; t < ntiles; t += gridDim.x) {
        int tn = t + gridDim.x;
        if (tn < ntiles) {
            fillX(xb_u32[buf ^ 1], tn);
            cp_async_commit();
        }

        const uint32_t xa_base = xb_u32[buf] + ((wm + lrow) * XP + lk8) * 2;

        float acc[8][4];
#pragma unroll
        for (int j = 0; j < 8; j++)
            acc[j][0] = acc[j][1] = acc[j][2] = acc[j][3] = 0.f;

#pragma unroll
        for (int ks = 0; ks < 8; ks++) {
            const int k0 = ks * 16;
            uint32_t a0, a1, a2, a3;
            ldsm_x4(xa_base + k0 * 2, a0, a1, a2, a3);
#pragma unroll
            for (int jp = 0; jp < 4; jp++) {
                uint32_t b0, b1, b2, b3;
                ldsm_x4_t(wb_base + (k0 * WP + jp * 16) * 2, b0, b1, b2, b3);
                mma16816(acc[2 * jp],     a0, a1, a2, a3, b0, b1);
                mma16816(acc[2 * jp + 1], a0, a1, a2, a3, b2, b3);
            }
        }

        // epilogue for tile t
        const int r0i = t * TM + wm + g;
#pragma unroll
        for (int j = 0; j < 8; j++) {
            int cidx = n0 + j * 8 + 2 * t4;
            if (r0i < n)
                *(half2*)(H + (size_t)r0i * FOUT + cidx) =
                    __floats2half2_rn(acc[j][0], acc[j][1]);
            if (r0i + 8 < n)
                *(half2*)(H + (size_t)(r0i + 8) * FOUT + cidx) =
                    __floats2half2_rn(acc[j][2], acc[j][3]);
        }

        if (tn < ntiles) cp_async_wait0();
        __syncthreads();
        buf ^= 1;
    }
}

// ---------------- aggregate: 32-edge batch loads + shfl broadcast --------------
// Warp per node. One coalesced LDG.64 fetches (srcrow,w) for 32 edges; the
// h-row gathers are issued 8-deep with all addresses known up front.

__global__ void agg128_k(const __half* __restrict__ h, const int2* __restrict__ ew,
                         const int* __restrict__ start, const float* __restrict__ bias,
                         __half* __restrict__ out, int n) {
    int node = (blockIdx.x * blockDim.x + threadIdx.x) >> 5;
    int lane = threadIdx.x & 31;
    if (node >= n) return;

    int s = start[node];
    int e = start[node + 1];
    const uint2* hb = (const uint2*)h;   // row = 32 uint2 (256B)

    float a0x = 0.f, a0y = 0.f, a0z = 0.f, a0w = 0.f;
    float a1x = 0.f, a1y = 0.f, a1z = 0.f, a1w = 0.f;

    for (int base = s; base < e; base += 32) {
        int idx = base + lane;
        int2 p = make_int2(0, 0);
        if (idx < e) p = __ldg(ew + idx);
        int cnt = e - base;
        if (cnt > 32) cnt = 32;

        int j = 0;
        for (; j + 8 <= cnt; j += 8) {
            uint2 v[8];
            float wg[8];
#pragma unroll
            for (int q = 0; q < 8; q++) {
                int rr = __shfl_sync(0xffffffffu, p.x, j + q);
                wg[q]  = __int_as_float(__shfl_sync(0xffffffffu, p.y, j + q));
                v[q] = __ldg(hb + (size_t)rr * 32 + lane);
            }
#pragma unroll
            for (int q = 0; q < 8; q++) {
                float2 f0 = __half22float2(*(const half2*)&v[q].x);
                float2 f1 = __half22float2(*(const half2*)&v[q].y);
                if (q & 1) {
                    a1x += f0.x * wg[q]; a1y += f0.y * wg[q];
                    a1z += f1.x * wg[q]; a1w += f1.y * wg[q];
                } else {
                    a0x += f0.x * wg[q]; a0y += f0.y * wg[q];
                    a0z += f1.x * wg[q]; a0w += f1.y * wg[q];
                }
            }
        }
        for (; j < cnt; j++) {
            int rr = __shfl_sync(0xffffffffu, p.x, j);
            float wq = __int_as_float(__shfl_sync(0xffffffffu, p.y, j));
            uint2 v = __ldg(hb + (size_t)rr * 32 + lane);
            float2 f0 = __half22float2(*(const half2*)&v.x);
            float2 f1 = __half22float2(*(const half2*)&v.y);
            a0x += f0.x * wq; a0y += f0.y * wq;
            a0z += f1.x * wq; a0w += f1.y * wq;
        }
    }

    float4 bv = __ldg((const float4*)bias + lane);
    a0x = fmaxf(a0x + a1x + bv.x, 0.f);
    a0y = fmaxf(a0y + a1y + bv.y, 0.f);
    a0z = fmaxf(a0z + a1z + bv.z, 0.f);
    a0w = fmaxf(a0w + a1w + bv.w, 0.f);

    half2 o0 = __floats2half2_rn(a0x, a0y);
    half2 o1 = __floats2half2_rn(a0z, a0w);
    uint2 ov;
    ov.x = *(const uint32_t*)&o0;
    ov.y = *(const uint32_t*)&o1;
    *((uint2*)out + (size_t)node * 32 + lane) = ov;
}

__global__ void agg64_k(const __half* __restrict__ h, const int2* __restrict__ ew,
                        const int* __restrict__ start, const float* __restrict__ bias,
                        float* __restrict__ out, int n) {
    int node = (blockIdx.x * blockDim.x + threadIdx.x) >> 5;
    int lane = threadIdx.x & 31;
    if (node >= n) return;

    int s = start[node];
    int e = start[node + 1];
    const half2* hb = (const half2*)h;   // row = 32 half2 (128B)

    float a0x = 0.f, a0y = 0.f, a1x = 0.f, a1y = 0.f;

    for (int base = s; base < e; base += 32) {
        int idx = base + lane;
        int2 p = make_int2(0, 0);
        if (idx < e) p = __ldg(ew + idx);
        int cnt = e - base;
        if (cnt > 32) cnt = 32;

        int j = 0;
        for (; j + 8 <= cnt; j += 8) {
            half2 v[8];
            float wg[8];
#pragma unroll
            for (int q = 0; q < 8; q++) {
                int rr = __shfl_sync(0xffffffffu, p.x, j + q);
                wg[q]  = __int_as_float(__shfl_sync(0xffffffffu, p.y, j + q));
                v[q] = __ldg(hb + (size_t)rr * 32 + lane);
            }
#pragma unroll
            for (int q = 0; q < 8; q++) {
                float2 f = __half22float2(v[q]);
                if (q & 1) { a1x += f.x * wg[q]; a1y += f.y * wg[q]; }
                else       { a0x += f.x * wg[q]; a0y += f.y * wg[q]; }
            }
        }
        for (; j < cnt; j++) {
            int rr = __shfl_sync(0xffffffffu, p.x, j);
            float wq = __int_as_float(__shfl_sync(0xffffffffu, p.y, j));
            float2 f = __half22float2(__ldg(hb + (size_t)rr * 32 + lane));
            a0x += f.x * wq; a0y += f.y * wq;
        }
    }

    float2 bv = __ldg((const float2*)bias + lane);
    a0x += a1x + bv.x;
    a0y += a1y + bv.y;
    *((float2*)(out + (size_t)node * 64) + lane) = make_float2(a0x, a0y);
}

// ---------------- launch ----------------

extern "C" void kernel_launch(void* const* d_in, const int* in_sizes, int n_in,
                              void* d_out, int out_size) {
    const float* x  = (const float*)d_in[0];
    const int*   ei = (const int*)d_in[1];      // int32 (JAX x64 disabled)
    const float* W1 = (const float*)d_in[2];
    const float* b1 = (const float*)d_in[3];
    const float* W2 = (const float*)d_in[4];
    const float* b2 = (const float*)d_in[5];
    const float* W3 = (const float*)d_in[6];
    const float* b3 = (const float*)d_in[7];
    float* out = (float*)d_out;

    const int N = in_sizes[0] / 128;
    const int E = in_sizes[1] / 2;
    const int* row = ei;
    const int* col = ei + E;

    int *deg, *start, *cursor, *bsums;
    int2* ew;
    float* dinv;
    __half *x16, *h, *act, *w1t, *w2t, *w3t;
    cudaGetSymbolAddress((void**)&deg,    g_deg);
    cudaGetSymbolAddress((void**)&dinv,   g_dinv);
    cudaGetSymbolAddress((void**)&start,  g_start);
    cudaGetSymbolAddress((void**)&cursor, g_cursor);
    cudaGetSymbolAddress((void**)&bsums,  g_bsums);
    cudaGetSymbolAddress((void**)&ew,     g_ew);
    cudaGetSymbolAddress((void**)&x16,    g_x16);
    cudaGetSymbolAddress((void**)&h,      g_h);
    cudaGetSymbolAddress((void**)&act,    g_act);
    cudaGetSymbolAddress((void**)&w1t,    g_w1t);
    cudaGetSymbolAddress((void**)&w2t,    g_w2t);
    cudaGetSymbolAddress((void**)&w3t,    g_w3t);

    const int SMEM128 = (2 * 64 * XP + 128 * WP) * 2;    // 69632 B -> 2-3 CTAs/SM
    const int SMEM64  = (2 * 128 * XP + 128 * WP) * 2;   // 104448 B -> 2 CTAs/SM
    cudaFuncSetAttribute(gemm_k<128>, cudaFuncAttributeMaxDynamicSharedMemorySize, SMEM128);
    cudaFuncSetAttribute(gemm_k<64>,  cudaFuncAttributeMaxDynamicSharedMemorySize, SMEM64);

    const int TB = 256;
    const int gN   = (N + TB - 1) / TB;
    const int gE   = (E + TB - 1) / TB;
    const int gW   = ((size_t)N * 32 + TB - 1) / TB;  // warp-per-node grid
    const int nt128 = (N + 63) / 64;                  // 1563 tiles
    const int nt64  = (N + 127) / 128;                // 782 tiles
    const int gP128 = 148 * 3;
    const int gP64  = 148 * 2;
    const int gC   = (N * 32 + TB - 1) / TB;          // cvt16
    const int nb   = (N + SCAN_B - 1) / SCAN_B;       // 98

    // gemm1 at launch index 3 (ncu samples there)
    zero_deg_k<<<gN, TB>>>(deg, N);                                  // 0
    cvt16_k<<<gC, TB>>>((const float4*)x, (uint2*)x16, N * 32);      // 1
    wprep_k<<<64, TB>>>(W1, w1t, 128 * 128);                         // 2
    gemm_k<128><<<gP128, TB, SMEM128>>>(x16, w1t, h, N, nt128);      // 3 <- profiled
    degree_k<<<gE, TB>>>(col, deg, E);                               // 4
    wprep_k<<<64, TB>>>(W2, w2t, 128 * 128);                         // 5
    wprep_k<<<32, TB>>>(W3, w3t, 128 * 64);                          // 6
    scan1_dinv_k<<<nb, SCAN_B>>>(deg, start, bsums, dinv, N);        // 7
    scan2_k<<<1, MAX_BLOCKS>>>(bsums, nb);                           // 8
    scan3_cursor_k<<<gN, TB>>>(start, bsums, cursor, N);             // 9
    fill_k<<<gE, TB>>>(row, col, dinv, cursor, ew, E);               // 10

    // ---- layer 1 ----
    agg128_k<<<gW, TB>>>(h, ew, start, b1, act, N);                  // 11
    // ---- layer 2 ----
    gemm_k<128><<<gP128, TB, SMEM128>>>(act, w2t, h, N, nt128);      // 12
    agg128_k<<<gW, TB>>>(h, ew, start, b2, act, N);                  // 13
    // ---- layer 3 ----
    gemm_k<64><<<gP64, TB, SMEM64>>>(act, w3t, h, N, nt64);          // 14
    agg64_k<<<gW, TB>>>(h, ew, start, b3, out, N);                   // 15
}

// round 14
// speedup vs baseline: 1.1310x; 1.1310x over previous
#include <cuda_runtime.h>
#include <cuda_fp16.h>
#include <cstdint>

// Problem constants (fixed by the dataset)
#define NN 100000
#define EE 1600000
#define SCAN_B 1024
#define MAX_BLOCKS 128   // ceil(NN/1024) = 98 <= 128

// Scratch (no cudaMalloc allowed)
__device__ int   g_deg[NN];
__device__ __align__(16) float g_dinv[NN];
__device__ int   g_start[NN + 1];
__device__ int   g_cursor[NN];
__device__ int   g_bsums[MAX_BLOCKS];
__device__ __align__(16) int2   g_ew[EE];                   // packed {srcrow, w bits}
__device__ __align__(16) __half g_x16[(size_t)NN * 128];    // fp16 copy of input x
__device__ __align__(16) __half g_h[(size_t)NN * 128];      // GEMM output (fp16)
__device__ __align__(16) __half g_act[(size_t)NN * 128];    // inter-layer activations (fp16)
__device__ __align__(16) __half g_w1t[128 * 128];           // W1 fp16 row-major
__device__ __align__(16) __half g_w2t[128 * 128];           // W2 fp16
__device__ __align__(16) __half g_w3t[128 * 64];            // W3 fp16

// ---------------- prologue ----------------

__global__ void zero_deg_k(int* __restrict__ p, int n) {
    int i = blockIdx.x * blockDim.x + threadIdx.x;
    if (i < n) p[i] = 0;
}

__global__ void cvt16_k(const float4* __restrict__ x, uint2* __restrict__ x16, int n4) {
    int i = blockIdx.x * blockDim.x + threadIdx.x;
    if (i < n4) {
        float4 f = __ldg(x + i);
        half2 a = __floats2half2_rn(f.x, f.y);
        half2 b = __floats2half2_rn(f.z, f.w);
        uint2 o;
        o.x = *(const uint32_t*)&a;
        o.y = *(const uint32_t*)&b;
        x16[i] = o;
    }
}

__global__ void wprep_k(const float* __restrict__ W, __half* __restrict__ Wt, int total) {
    int i = blockIdx.x * blockDim.x + threadIdx.x;
    if (i < total) Wt[i] = __float2half_rn(W[i]);
}

__global__ void degree_k(const int* __restrict__ col, int* __restrict__ deg, int E) {
    int e = blockIdx.x * blockDim.x + threadIdx.x;
    if (e < E) atomicAdd(&deg[col[e]], 1);
}

__global__ void scan1_dinv_k(const int* __restrict__ deg, int* __restrict__ start,
                             int* __restrict__ bsums, float* __restrict__ dinv, int n) {
    __shared__ int s[SCAN_B];
    int i = blockIdx.x * SCAN_B + threadIdx.x;
    int v = (i < n) ? deg[i] : 0;
    if (i < n) dinv[i] = (v > 0) ? rsqrtf((float)v) : 0.0f;
    s[threadIdx.x] = v;
    __syncthreads();
    for (int off = 1; off < SCAN_B; off <<= 1) {
        int t = (threadIdx.x >= off) ? s[threadIdx.x - off] : 0;
        __syncthreads();
        s[threadIdx.x] += t;
        __syncthreads();
    }
    if (i < n) start[i + 1] = s[threadIdx.x];
    if (threadIdx.x == SCAN_B - 1) bsums[blockIdx.x] = s[SCAN_B - 1];
}

__global__ void scan2_k(int* __restrict__ bsums, int nb) {
    __shared__ int s[MAX_BLOCKS];
    int v = (threadIdx.x < nb) ? bsums[threadIdx.x] : 0;
    s[threadIdx.x] = v;
    __syncthreads();
    for (int off = 1; off < MAX_BLOCKS; off <<= 1) {
        int t = (threadIdx.x >= off) ? s[threadIdx.x - off] : 0;
        __syncthreads();
        s[threadIdx.x] += t;
        __syncthreads();
    }
    if (threadIdx.x < nb) bsums[threadIdx.x] = s[threadIdx.x] - v;  // exclusive
}

__global__ void scan3_cursor_k(int* __restrict__ start, const int* __restrict__ bsums,
                               int* __restrict__ cursor, int n) {
    int i = blockIdx.x * blockDim.x + threadIdx.x;
    if (i < n) {
        int v = start[i + 1] + bsums[i >> 10];
        start[i + 1] = v;
        if (i + 1 < n) cursor[i + 1] = v;
        if (i == 0) { start[0] = 0; cursor[0] = 0; }
    }
}

__global__ void fill_k(const int* __restrict__ row, const int* __restrict__ col,
                       const float* __restrict__ dinv, int* __restrict__ cursor,
                       int2* __restrict__ ew, int E) {
    int e = blockIdx.x * blockDim.x + threadIdx.x;
    if (e < E) {
        int r = row[e];
        int c = col[e];
        int pos = atomicAdd(&cursor[c], 1);
        ew[pos] = make_int2(r, __float_as_int(dinv[r] * dinv[c]));
    }
}

// ---------------- tensor-core GEMM (mma.sync fallback HMMA) ---------------------
// H[n,FOUT] = fp16( X16[n,128] @ W16[128,FOUT] ), fp32 accumulate.
// Block: TM x FOUT (TM=64 for FOUT=128; TM=128 for FOUT=64), 8 warps, warp tile
// 16x64. cp.async fills (both operands fp16), ldmatrix frags. (round-12 proven)

__device__ __forceinline__ uint32_t smem_u32(const void* p) {
    uint32_t a;
    asm("{ .reg .u64 t; cvta.to.shared.u64 t, %1; cvt.u32.u64 %0, t; }" : "=r"(a) : "l"(p));
    return a;
}

__device__ __forceinline__ void cp_async16(uint32_t dst, const void* src, uint32_t sz) {
    asm volatile("cp.async.cg.shared.global [%0], [%1], 16, %2;"
                 :: "r"(dst), "l"(src), "r"(sz) : "memory");
}

__device__ __forceinline__ void cp_async_wait_all() {
    asm volatile("cp.async.commit_group;\n\tcp.async.wait_group 0;" ::: "memory");
}

__device__ __forceinline__ void mma16816(float* c,
    uint32_t a0, uint32_t a1, uint32_t a2, uint32_t a3,
    uint32_t b0, uint32_t b1) {
    asm volatile(
        "mma.sync.aligned.m16n8k16.row.col.f32.f16.f16.f32 "
        "{%0,%1,%2,%3}, {%4,%5,%6,%7}, {%8,%9}, {%0,%1,%2,%3};"
        : "+f"(c[0]), "+f"(c[1]), "+f"(c[2]), "+f"(c[3])
        : "r"(a0), "r"(a1), "r"(a2), "r"(a3), "r"(b0), "r"(b1));
}

__device__ __forceinline__ void ldsm_x4(uint32_t addr, uint32_t& r0, uint32_t& r1,
                                        uint32_t& r2, uint32_t& r3) {
    asm volatile("ldmatrix.sync.aligned.m8n8.x4.shared.b16 {%0,%1,%2,%3}, [%4];"
                 : "=r"(r0), "=r"(r1), "=r"(r2), "=r"(r3) : "r"(addr));
}

__device__ __forceinline__ void ldsm_x4_t(uint32_t addr, uint32_t& r0, uint32_t& r1,
                                          uint32_t& r2, uint32_t& r3) {
    asm volatile("ldmatrix.sync.aligned.m8n8.x4.trans.shared.b16 {%0,%1,%2,%3}, [%4];"
                 : "=r"(r0), "=r"(r1), "=r"(r2), "=r"(r3) : "r"(addr));
}

#define XP 136
#define WP 136

template <int FOUT>
__global__ __launch_bounds__(256, 3)
void gemm_k(const __half* __restrict__ X, const __half* __restrict__ Wt,
            __half* __restrict__ H, int n) {
    constexpr int TM = (FOUT == 128) ? 64 : 128;  // rows per block
    constexpr int NW = FOUT / 64;                 // warps along N (2 or 1)

    extern __shared__ __half smh[];
    __half* Xh  = smh;               // TM x XP
    __half* Wsm = smh + TM * XP;     // 128 x WP, row-major [k][c]

    const int tid  = threadIdx.x;
    const int warp = tid >> 5;
    const int lane = tid & 31;
    const int g = lane >> 2;       // 0..7
    const int t = lane & 3;        // 0..3
    const int row0 = blockIdx.x * TM;

    const uint32_t xh_base = smem_u32(Xh);
    const uint32_t wm_base = smem_u32(Wsm);

    // X fill via cp.async: TM*16 chunks of 16B
#pragma unroll
    for (int u = tid; u < TM * 16; u += 256) {
        int r = u >> 4, m = u & 15;
        bool ok = (row0 + r < n);
        const __half* src = X + (size_t)(ok ? (row0 + r) : 0) * 128 + m * 8;
        cp_async16(xh_base + (r * XP + m * 8) * 2, src, ok ? 16u : 0u);
    }
    // W fill via cp.async
#pragma unroll
    for (int u = tid; u < 128 * (FOUT / 8); u += 256) {
        int k = u / (FOUT / 8), c8 = (u % (FOUT / 8)) * 8;
        cp_async16(wm_base + (k * WP + c8) * 2, Wt + k * FOUT + c8, 16u);
    }
    cp_async_wait_all();
    __syncthreads();

    const int wm = (warp / NW) * 16;      // warp row base
    const int n0 = (warp % NW) * 64;      // warp col base

    const int lrow = lane & 15;
    const int lk8  = ((lane >> 4) & 1) * 8;
    uint32_t xa_base = xh_base + ((wm + lrow) * XP + lk8) * 2;
    uint32_t wb_base = wm_base + (lrow * WP + n0 + lk8) * 2;

    float acc[8][4];
#pragma unroll
    for (int j = 0; j < 8; j++)
        acc[j][0] = acc[j][1] = acc[j][2] = acc[j][3] = 0.f;

#pragma unroll
    for (int ks = 0; ks < 8; ks++) {
        const int k0 = ks * 16;
        uint32_t a0, a1, a2, a3;
        ldsm_x4(xa_base + k0 * 2, a0, a1, a2, a3);
#pragma unroll
        for (int jp = 0; jp < 4; jp++) {
            uint32_t b0, b1, b2, b3;
            ldsm_x4_t(wb_base + (k0 * WP + jp * 16) * 2, b0, b1, b2, b3);
            mma16816(acc[2 * jp],     a0, a1, a2, a3, b0, b1);
            mma16816(acc[2 * jp + 1], a0, a1, a2, a3, b2, b3);
        }
    }

    // epilogue: c0,c1 -> (row wm+g, col n0+8j+2t); c2,c3 -> row +8
    const int r0i = row0 + wm + g;
#pragma unroll
    for (int j = 0; j < 8; j++) {
        int cidx = n0 + j * 8 + 2 * t;
        if (r0i < n)
            *(half2*)(H + (size_t)r0i * FOUT + cidx) =
                __floats2half2_rn(acc[j][0], acc[j][1]);
        if (r0i + 8 < n)
            *(half2*)(H + (size_t)(r0i + 8) * FOUT + cidx) =
                __floats2half2_rn(acc[j][2], acc[j][3]);
    }
}

// ---------------- aggregate (fp16 gather, fp32 accumulate, MLP=8) ----------------

__global__ void agg128_k(const __half* __restrict__ h, const int2* __restrict__ ew,
                         const int* __restrict__ start, const float* __restrict__ bias,
                         __half* __restrict__ out, int n) {
    int node = (blockIdx.x * blockDim.x + threadIdx.x) >> 5;
    int lane = threadIdx.x & 31;
    if (node >= n) return;

    int s = start[node];
    int e = start[node + 1];
    const uint2* hb = (const uint2*)h;   // 8B = 4 halves per lane; row = 32 uint2

    float a0x = 0.f, a0y = 0.f, a0z = 0.f, a0w = 0.f;
    float a1x = 0.f, a1y = 0.f, a1z = 0.f, a1w = 0.f;

    int k = s;
    // 8 edges in flight
    for (; k + 8 <= e; k += 8) {
        int2 p[8];
#pragma unroll
        for (int q = 0; q < 8; q++) p[q] = __ldg(ew + k + q);
        uint2 v[8];
#pragma unroll
        for (int q = 0; q < 8; q++) v[q] = __ldg(hb + (size_t)p[q].x * 32 + lane);
#pragma unroll
        for (int q = 0; q < 8; q++) {
            float wq = __int_as_float(p[q].y);
            float2 f0 = __half22float2(*(const half2*)&v[q].x);
            float2 f1 = __half22float2(*(const half2*)&v[q].y);
            if (q & 1) {
                a1x += f0.x * wq; a1y += f0.y * wq;
                a1z += f1.x * wq; a1w += f1.y * wq;
            } else {
                a0x += f0.x * wq; a0y += f0.y * wq;
                a0z += f1.x * wq; a0w += f1.y * wq;
            }
        }
    }
    // 4-edge step
    for (; k + 4 <= e; k += 4) {
        int2 p[4];
#pragma unroll
        for (int q = 0; q < 4; q++) p[q] = __ldg(ew + k + q);
        uint2 v[4];
#pragma unroll
        for (int q = 0; q < 4; q++) v[q] = __ldg(hb + (size_t)p[q].x * 32 + lane);
#pragma unroll
        for (int q = 0; q < 4; q++) {
            float wq = __int_as_float(p[q].y);
            float2 f0 = __half22float2(*(const half2*)&v[q].x);
            float2 f1 = __half22float2(*(const half2*)&v[q].y);
            if (q & 1) {
                a1x += f0.x * wq; a1y += f0.y * wq;
                a1z += f1.x * wq; a1w += f1.y * wq;
            } else {
                a0x += f0.x * wq; a0y += f0.y * wq;
                a0z += f1.x * wq; a0w += f1.y * wq;
            }
        }
    }
    for (; k < e; k++) {
        int2 p0 = __ldg(ew + k);
        float w0 = __int_as_float(p0.y);
        uint2 v0 = __ldg(hb + (size_t)p0.x * 32 + lane);
        float2 f0 = __half22float2(*(const half2*)&v0.x);
        float2 f1 = __half22float2(*(const half2*)&v0.y);
        a0x += f0.x * w0; a0y += f0.y * w0;
        a0z += f1.x * w0; a0w += f1.y * w0;
    }

    float4 bv = __ldg((const float4*)bias + lane);
    a0x = fmaxf(a0x + a1x + bv.x, 0.f);
    a0y = fmaxf(a0y + a1y + bv.y, 0.f);
    a0z = fmaxf(a0z + a1z + bv.z, 0.f);
    a0w = fmaxf(a0w + a1w + bv.w, 0.f);

    half2 o0 = __floats2half2_rn(a0x, a0y);
    half2 o1 = __floats2half2_rn(a0z, a0w);
    uint2 ov;
    ov.x = *(const uint32_t*)&o0;
    ov.y = *(const uint32_t*)&o1;
    *((uint2*)out + (size_t)node * 32 + lane) = ov;
}

__global__ void agg64_k(const __half* __restrict__ h, const int2* __restrict__ ew,
                        const int* __restrict__ start, const float* __restrict__ bias,
                        float* __restrict__ out, int n) {
    int node = (blockIdx.x * blockDim.x + threadIdx.x) >> 5;
    int lane = threadIdx.x & 31;
    if (node >= n) return;

    int s = start[node];
    int e = start[node + 1];
    const half2* hb = (const half2*)h;   // row = 32 half2

    float a0x = 0.f, a0y = 0.f, a1x = 0.f, a1y = 0.f;

    int k = s;
    for (; k + 8 <= e; k += 8) {
        int2 p[8];
#pragma unroll
        for (int q = 0; q < 8; q++) p[q] = __ldg(ew + k + q);
        half2 v[8];
#pragma unroll
        for (int q = 0; q < 8; q++) v[q] = __ldg(hb + (size_t)p[q].x * 32 + lane);
#pragma unroll
        for (int q = 0; q < 8; q++) {
            float wq = __int_as_float(p[q].y);
            float2 f = __half22float2(v[q]);
            if (q & 1) { a1x += f.x * wq; a1y += f.y * wq; }
            else       { a0x += f.x * wq; a0y += f.y * wq; }
        }
    }
    for (; k + 4 <= e; k += 4) {
        int2 p[4];
#pragma unroll
        for (int q = 0; q < 4; q++) p[q] = __ldg(ew + k + q);
        half2 v[4];
#pragma unroll
        for (int q = 0; q < 4; q++) v[q] = __ldg(hb + (size_t)p[q].x * 32 + lane);
#pragma unroll
        for (int q = 0; q < 4; q++) {
            float wq = __int_as_float(p[q].y);
            float2 f = __half22float2(v[q]);
            if (q & 1) { a1x += f.x * wq; a1y += f.y * wq; }
            else       { a0x += f.x * wq; a0y += f.y * wq; }
        }
    }
    for (; k < e; k++) {
        int2 p0 = __ldg(ew + k);
        float w0 = __int_as_float(p0.y);
        float2 f = __half22float2(__ldg(hb + (size_t)p0.x * 32 + lane));
        a0x += f.x * w0; a0y += f.y * w0;
    }

    float2 bv = __ldg((const float2*)bias + lane);
    a0x += a1x + bv.x;
    a0y += a1y + bv.y;
    *((float2*)(out + (size_t)node * 64) + lane) = make_float2(a0x, a0y);
}

// ---------------- launch ----------------

extern "C" void kernel_launch(void* const* d_in, const int* in_sizes, int n_in,
                              void* d_out, int out_size) {
    const float* x  = (const float*)d_in[0];
    const int*   ei = (const int*)d_in[1];      // int32 (JAX x64 disabled)
    const float* W1 = (const float*)d_in[2];
    const float* b1 = (const float*)d_in[3];
    const float* W2 = (const float*)d_in[4];
    const float* b2 = (const float*)d_in[5];
    const float* W3 = (const float*)d_in[6];
    const float* b3 = (const float*)d_in[7];
    float* out = (float*)d_out;

    const int N = in_sizes[0] / 128;
    const int E = in_sizes[1] / 2;
    const int* row = ei;
    const int* col = ei + E;

    int *deg, *start, *cursor, *bsums;
    int2* ew;
    float* dinv;
    __half *x16, *h, *act, *w1t, *w2t, *w3t;
    cudaGetSymbolAddress((void**)&deg,    g_deg);
    cudaGetSymbolAddress((void**)&dinv,   g_dinv);
    cudaGetSymbolAddress((void**)&start,  g_start);
    cudaGetSymbolAddress((void**)&cursor, g_cursor);
    cudaGetSymbolAddress((void**)&bsums,  g_bsums);
    cudaGetSymbolAddress((void**)&ew,     g_ew);
    cudaGetSymbolAddress((void**)&x16,    g_x16);
    cudaGetSymbolAddress((void**)&h,      g_h);
    cudaGetSymbolAddress((void**)&act,    g_act);
    cudaGetSymbolAddress((void**)&w1t,    g_w1t);
    cudaGetSymbolAddress((void**)&w2t,    g_w2t);
    cudaGetSymbolAddress((void**)&w3t,    g_w3t);

    const int SMEM128 = (64 * XP + 128 * WP) * 2;    // 52224 B
    const int SMEM64  = (128 * XP + 128 * WP) * 2;   // 69632 B
    cudaFuncSetAttribute(gemm_k<128>, cudaFuncAttributeMaxDynamicSharedMemorySize, SMEM128);
    cudaFuncSetAttribute(gemm_k<64>,  cudaFuncAttributeMaxDynamicSharedMemorySize, SMEM64);

    const int TB = 256;
    const int gN    = (N + TB - 1) / TB;
    const int gE    = (E + TB - 1) / TB;
    const int gW    = ((size_t)N * 32 + TB - 1) / TB;  // warp-per-node grid
    const int gG128 = (N + 63) / 64;                   // 64-row tiles
    const int gG64  = (N + 127) / 128;                 // 128-row tiles
    const int gC    = (N * 32 + TB - 1) / TB;          // cvt16
    const int nb    = (N + SCAN_B - 1) / SCAN_B;       // 98

    // gemm1 at launch index 3 (ncu samples there)
    zero_deg_k<<<gN, TB>>>(deg, N);                                  // 0
    cvt16_k<<<gC, TB>>>((const float4*)x, (uint2*)x16, N * 32);      // 1
    wprep_k<<<64, TB>>>(W1, w1t, 128 * 128);                         // 2
    gemm_k<128><<<gG128, TB, SMEM128>>>(x16, w1t, h, N);             // 3 <- profiled
    degree_k<<<gE, TB>>>(col, deg, E);                               // 4
    wprep_k<<<64, TB>>>(W2, w2t, 128 * 128);                         // 5
    wprep_k<<<32, TB>>>(W3, w3t, 128 * 64);                          // 6
    scan1_dinv_k<<<nb, SCAN_B>>>(deg, start, bsums, dinv, N);        // 7
    scan2_k<<<1, MAX_BLOCKS>>>(bsums, nb);                           // 8
    scan3_cursor_k<<<gN, TB>>>(start, bsums, cursor, N);             // 9
    fill_k<<<gE, TB>>>(row, col, dinv, cursor, ew, E);               // 10

    // ---- layer 1 ----
    agg128_k<<<gW, TB>>>(h, ew, start, b1, act, N);                  // 11
    // ---- layer 2 ----
    gemm_k<128><<<gG128, TB, SMEM128>>>(act, w2t, h, N);             // 12
    agg128_k<<<gW, TB>>>(h, ew, start, b2, act, N);                  // 13
    // ---- layer 3 ----
    gemm_k<64><<<gG64, TB, SMEM64>>>(act, w3t, h, N);                // 14
    agg64_k<<<gW, TB>>>(h, ew, start, b3, out, N);                   // 15
}

// round 15
// speedup vs baseline: 1.1332x; 1.0019x over previous
#include <cuda_runtime.h>
#include <cuda_fp16.h>
#include <cstdint>

// Problem constants (fixed by the dataset)
#define NN 100000
#define EE 1600000
#define SCAN_B 1024
#define MAX_BLOCKS 128   // ceil(NN/1024) = 98 <= 128

// Scratch (no cudaMalloc allowed)
__device__ int   g_deg[NN];
__device__ __align__(16) float g_dinv[NN];
__device__ int   g_start[NN + 1];
__device__ int   g_cursor[NN];
__device__ int   g_bsums[MAX_BLOCKS];
__device__ __align__(16) int2   g_ew[EE];                   // packed {srcrow, w bits}
__device__ __align__(16) __half g_x16[(size_t)NN * 128];    // fp16 copy of input x
__device__ __align__(16) __half g_h[(size_t)NN * 128];      // GEMM output (fp16)
__device__ __align__(16) __half g_act[(size_t)NN * 128];    // inter-layer activations (fp16)
__device__ __align__(16) __half g_w1t[128 * 128];           // W1 fp16 row-major
__device__ __align__(16) __half g_w2t[128 * 128];           // W2 fp16
__device__ __align__(16) __half g_w3t[128 * 64];            // W3 fp16

// ---------------- fused prep: zero deg + W1/W2/W3 fp16 + x fp16 ----------------
// Index space: [0, NN)                 -> deg = 0
//              [NN, NN+16384)          -> W1 cvt
//              [+16384)                -> W2 cvt
//              [+8192)                 -> W3 cvt
//              [.., +NN*32)            -> x cvt (float4 granules)

#define PREP_W1 (NN)
#define PREP_W2 (PREP_W1 + 128 * 128)
#define PREP_W3 (PREP_W2 + 128 * 128)
#define PREP_X  (PREP_W3 + 128 * 64)
#define PREP_TOTAL (PREP_X + NN * 32)

__global__ void prep_k(const float* __restrict__ x, const float* __restrict__ W1,
                       const float* __restrict__ W2, const float* __restrict__ W3,
                       int* __restrict__ deg, __half* __restrict__ w1t,
                       __half* __restrict__ w2t, __half* __restrict__ w3t,
                       uint2* __restrict__ x16) {
    int i = blockIdx.x * blockDim.x + threadIdx.x;
    if (i < PREP_W1) {
        deg[i] = 0;
    } else if (i < PREP_W2) {
        int j = i - PREP_W1;
        w1t[j] = __float2half_rn(W1[j]);
    } else if (i < PREP_W3) {
        int j = i - PREP_W2;
        w2t[j] = __float2half_rn(W2[j]);
    } else if (i < PREP_X) {
        int j = i - PREP_W3;
        w3t[j] = __float2half_rn(W3[j]);
    } else if (i < PREP_TOTAL) {
        int j = i - PREP_X;
        float4 f = __ldg((const float4*)x + j);
        half2 a = __floats2half2_rn(f.x, f.y);
        half2 b = __floats2half2_rn(f.z, f.w);
        uint2 o;
        o.x = *(const uint32_t*)&a;
        o.y = *(const uint32_t*)&b;
        x16[j] = o;
    }
}

__global__ void degree_k(const int* __restrict__ col, int* __restrict__ deg, int E) {
    int e = blockIdx.x * blockDim.x + threadIdx.x;
    if (e < E) atomicAdd(&deg[col[e]], 1);
}

__global__ void scan1_dinv_k(const int* __restrict__ deg, int* __restrict__ start,
                             int* __restrict__ bsums, float* __restrict__ dinv, int n) {
    __shared__ int s[SCAN_B];
    int i = blockIdx.x * SCAN_B + threadIdx.x;
    int v = (i < n) ? deg[i] : 0;
    if (i < n) dinv[i] = (v > 0) ? rsqrtf((float)v) : 0.0f;
    s[threadIdx.x] = v;
    __syncthreads();
    for (int off = 1; off < SCAN_B; off <<= 1) {
        int t = (threadIdx.x >= off) ? s[threadIdx.x - off] : 0;
        __syncthreads();
        s[threadIdx.x] += t;
        __syncthreads();
    }
    if (i < n) start[i + 1] = s[threadIdx.x];
    if (threadIdx.x == SCAN_B - 1) bsums[blockIdx.x] = s[SCAN_B - 1];
}

__global__ void scan2_k(int* __restrict__ bsums, int nb) {
    __shared__ int s[MAX_BLOCKS];
    int v = (threadIdx.x < nb) ? bsums[threadIdx.x] : 0;
    s[threadIdx.x] = v;
    __syncthreads();
    for (int off = 1; off < MAX_BLOCKS; off <<= 1) {
        int t = (threadIdx.x >= off) ? s[threadIdx.x - off] : 0;
        __syncthreads();
        s[threadIdx.x] += t;
        __syncthreads();
    }
    if (threadIdx.x < nb) bsums[threadIdx.x] = s[threadIdx.x] - v;  // exclusive
}

__global__ void scan3_cursor_k(int* __restrict__ start, const int* __restrict__ bsums,
                               int* __restrict__ cursor, int n) {
    int i = blockIdx.x * blockDim.x + threadIdx.x;
    if (i < n) {
        int v = start[i + 1] + bsums[i >> 10];
        start[i + 1] = v;
        if (i + 1 < n) cursor[i + 1] = v;
        if (i == 0) { start[0] = 0; cursor[0] = 0; }
    }
}

__global__ void fill_k(const int* __restrict__ row, const int* __restrict__ col,
                       const float* __restrict__ dinv, int* __restrict__ cursor,
                       int2* __restrict__ ew, int E) {
    int e = blockIdx.x * blockDim.x + threadIdx.x;
    if (e < E) {
        int r = row[e];
        int c = col[e];
        int pos = atomicAdd(&cursor[c], 1);
        ew[pos] = make_int2(r, __float_as_int(dinv[r] * dinv[c]));
    }
}

// ---------------- tensor-core GEMM (mma.sync fallback HMMA) ---------------------

__device__ __forceinline__ uint32_t smem_u32(const void* p) {
    uint32_t a;
    asm("{ .reg .u64 t; cvta.to.shared.u64 t, %1; cvt.u32.u64 %0, t; }" : "=r"(a) : "l"(p));
    return a;
}

__device__ __forceinline__ void cp_async16(uint32_t dst, const void* src, uint32_t sz) {
    asm volatile("cp.async.cg.shared.global [%0], [%1], 16, %2;"
                 :: "r"(dst), "l"(src), "r"(sz) : "memory");
}

__device__ __forceinline__ void cp_async_wait_all() {
    asm volatile("cp.async.commit_group;\n\tcp.async.wait_group 0;" ::: "memory");
}

__device__ __forceinline__ void mma16816(float* c,
    uint32_t a0, uint32_t a1, uint32_t a2, uint32_t a3,
    uint32_t b0, uint32_t b1) {
    asm volatile(
        "mma.sync.aligned.m16n8k16.row.col.f32.f16.f16.f32 "
        "{%0,%1,%2,%3}, {%4,%5,%6,%7}, {%8,%9}, {%0,%1,%2,%3};"
        : "+f"(c[0]), "+f"(c[1]), "+f"(c[2]), "+f"(c[3])
        : "r"(a0), "r"(a1), "r"(a2), "r"(a3), "r"(b0), "r"(b1));
}

__device__ __forceinline__ void ldsm_x4(uint32_t addr, uint32_t& r0, uint32_t& r1,
                                        uint32_t& r2, uint32_t& r3) {
    asm volatile("ldmatrix.sync.aligned.m8n8.x4.shared.b16 {%0,%1,%2,%3}, [%4];"
                 : "=r"(r0), "=r"(r1), "=r"(r2), "=r"(r3) : "r"(addr));
}

__device__ __forceinline__ void ldsm_x4_t(uint32_t addr, uint32_t& r0, uint32_t& r1,
                                          uint32_t& r2, uint32_t& r3) {
    asm volatile("ldmatrix.sync.aligned.m8n8.x4.trans.shared.b16 {%0,%1,%2,%3}, [%4];"
                 : "=r"(r0), "=r"(r1), "=r"(r2), "=r"(r3) : "r"(addr));
}

#define XP 136
#define WP 136

template <int FOUT>
__global__ __launch_bounds__(256, 4)
void gemm_k(const __half* __restrict__ X, const __half* __restrict__ Wt,
            __half* __restrict__ H, int n) {
    constexpr int TM = (FOUT == 128) ? 64 : 128;  // rows per block
    constexpr int NW = FOUT / 64;                 // warps along N (2 or 1)

    extern __shared__ __half smh[];
    __half* Xh  = smh;               // TM x XP
    __half* Wsm = smh + TM * XP;     // 128 x WP, row-major [k][c]

    const int tid  = threadIdx.x;
    const int warp = tid >> 5;
    const int lane = tid & 31;
    const int g = lane >> 2;       // 0..7
    const int t = lane & 3;        // 0..3
    const int row0 = blockIdx.x * TM;

    const uint32_t xh_base = smem_u32(Xh);
    const uint32_t wm_base = smem_u32(Wsm);

    // X fill via cp.async: TM*16 chunks of 16B
#pragma unroll
    for (int u = tid; u < TM * 16; u += 256) {
        int r = u >> 4, m = u & 15;
        bool ok = (row0 + r < n);
        const __half* src = X + (size_t)(ok ? (row0 + r) : 0) * 128 + m * 8;
        cp_async16(xh_base + (r * XP + m * 8) * 2, src, ok ? 16u : 0u);
    }
    // W fill via cp.async
#pragma unroll
    for (int u = tid; u < 128 * (FOUT / 8); u += 256) {
        int k = u / (FOUT / 8), c8 = (u % (FOUT / 8)) * 8;
        cp_async16(wm_base + (k * WP + c8) * 2, Wt + k * FOUT + c8, 16u);
    }
    cp_async_wait_all();
    __syncthreads();

    const int wm = (warp / NW) * 16;      // warp row base
    const int n0 = (warp % NW) * 64;      // warp col base

    const int lrow = lane & 15;
    const int lk8  = ((lane >> 4) & 1) * 8;
    uint32_t xa_base = xh_base + ((wm + lrow) * XP + lk8) * 2;
    uint32_t wb_base = wm_base + (lrow * WP + n0 + lk8) * 2;

    float acc[8][4];
#pragma unroll
    for (int j = 0; j < 8; j++)
        acc[j][0] = acc[j][1] = acc[j][2] = acc[j][3] = 0.f;

#pragma unroll
    for (int ks = 0; ks < 8; ks++) {
        const int k0 = ks * 16;
        uint32_t a0, a1, a2, a3;
        ldsm_x4(xa_base + k0 * 2, a0, a1, a2, a3);
#pragma unroll
        for (int jp = 0; jp < 4; jp++) {
            uint32_t b0, b1, b2, b3;
            ldsm_x4_t(wb_base + (k0 * WP + jp * 16) * 2, b0, b1, b2, b3);
            mma16816(acc[2 * jp],     a0, a1, a2, a3, b0, b1);
            mma16816(acc[2 * jp + 1], a0, a1, a2, a3, b2, b3);
        }
    }

    // epilogue: c0,c1 -> (row wm+g, col n0+8j+2t); c2,c3 -> row +8
    const int r0i = row0 + wm + g;
#pragma unroll
    for (int j = 0; j < 8; j++) {
        int cidx = n0 + j * 8 + 2 * t;
        if (r0i < n)
            *(half2*)(H + (size_t)r0i * FOUT + cidx) =
                __floats2half2_rn(acc[j][0], acc[j][1]);
        if (r0i + 8 < n)
            *(half2*)(H + (size_t)(r0i + 8) * FOUT + cidx) =
                __floats2half2_rn(acc[j][2], acc[j][3]);
    }
}

// ---------------- aggregate (fp16 gather, fp32 accumulate, MLP=8) ----------------

__global__ void agg128_k(const __half* __restrict__ h, const int2* __restrict__ ew,
                         const int* __restrict__ start, const float* __restrict__ bias,
                         __half* __restrict__ out, int n) {
    int node = (blockIdx.x * blockDim.x + threadIdx.x) >> 5;
    int lane = threadIdx.x & 31;
    if (node >= n) return;

    int s = start[node];
    int e = start[node + 1];
    const uint2* hb = (const uint2*)h;   // 8B = 4 halves per lane; row = 32 uint2

    float a0x = 0.f, a0y = 0.f, a0z = 0.f, a0w = 0.f;
    float a1x = 0.f, a1y = 0.f, a1z = 0.f, a1w = 0.f;

    int k = s;
    for (; k + 8 <= e; k += 8) {
        int2 p[8];
#pragma unroll
        for (int q = 0; q < 8; q++) p[q] = __ldg(ew + k + q);
        uint2 v[8];
#pragma unroll
        for (int q = 0; q < 8; q++) v[q] = __ldg(hb + (size_t)p[q].x * 32 + lane);
#pragma unroll
        for (int q = 0; q < 8; q++) {
            float wq = __int_as_float(p[q].y);
            float2 f0 = __half22float2(*(const half2*)&v[q].x);
            float2 f1 = __half22float2(*(const half2*)&v[q].y);
            if (q & 1) {
                a1x += f0.x * wq; a1y += f0.y * wq;
                a1z += f1.x * wq; a1w += f1.y * wq;
            } else {
                a0x += f0.x * wq; a0y += f0.y * wq;
                a0z += f1.x * wq; a0w += f1.y * wq;
            }
        }
    }
    for (; k + 4 <= e; k += 4) {
        int2 p[4];
#pragma unroll
        for (int q = 0; q < 4; q++) p[q] = __ldg(ew + k + q);
        uint2 v[4];
#pragma unroll
        for (int q = 0; q < 4; q++) v[q] = __ldg(hb + (size_t)p[q].x * 32 + lane);
#pragma unroll
        for (int q = 0; q < 4; q++) {
            float wq = __int_as_float(p[q].y);
            float2 f0 = __half22float2(*(const half2*)&v[q].x);
            float2 f1 = __half22float2(*(const half2*)&v[q].y);
            if (q & 1) {
                a1x += f0.x * wq; a1y += f0.y * wq;
                a1z += f1.x * wq; a1w += f1.y * wq;
            } else {
                a0x += f0.x * wq; a0y += f0.y * wq;
                a0z += f1.x * wq; a0w += f1.y * wq;
            }
        }
    }
    for (; k < e; k++) {
        int2 p0 = __ldg(ew + k);
        float w0 = __int_as_float(p0.y);
        uint2 v0 = __ldg(hb + (size_t)p0.x * 32 + lane);
        float2 f0 = __half22float2(*(const half2*)&v0.x);
        float2 f1 = __half22float2(*(const half2*)&v0.y);
        a0x += f0.x * w0; a0y += f0.y * w0;
        a0z += f1.x * w0; a0w += f1.y * w0;
    }

    float4 bv = __ldg((const float4*)bias + lane);
    a0x = fmaxf(a0x + a1x + bv.x, 0.f);
    a0y = fmaxf(a0y + a1y + bv.y, 0.f);
    a0z = fmaxf(a0z + a1z + bv.z, 0.f);
    a0w = fmaxf(a0w + a1w + bv.w, 0.f);

    half2 o0 = __floats2half2_rn(a0x, a0y);
    half2 o1 = __floats2half2_rn(a0z, a0w);
    uint2 ov;
    ov.x = *(const uint32_t*)&o0;
    ov.y = *(const uint32_t*)&o1;
    *((uint2*)out + (size_t)node * 32 + lane) = ov;
}

__global__ void agg64_k(const __half* __restrict__ h, const int2* __restrict__ ew,
                        const int* __restrict__ start, const float* __restrict__ bias,
                        float* __restrict__ out, int n) {
    int node = (blockIdx.x * blockDim.x + threadIdx.x) >> 5;
    int lane = threadIdx.x & 31;
    if (node >= n) return;

    int s = start[node];
    int e = start[node + 1];
    const half2* hb = (const half2*)h;   // row = 32 half2

    float a0x = 0.f, a0y = 0.f, a1x = 0.f, a1y = 0.f;

    int k = s;
    for (; k + 8 <= e; k += 8) {
        int2 p[8];
#pragma unroll
        for (int q = 0; q < 8; q++) p[q] = __ldg(ew + k + q);
        half2 v[8];
#pragma unroll
        for (int q = 0; q < 8; q++) v[q] = __ldg(hb + (size_t)p[q].x * 32 + lane);
#pragma unroll
        for (int q = 0; q < 8; q++) {
            float wq = __int_as_float(p[q].y);
            float2 f = __half22float2(v[q]);
            if (q & 1) { a1x += f.x * wq; a1y += f.y * wq; }
            else       { a0x += f.x * wq; a0y += f.y * wq; }
        }
    }
    for (; k + 4 <= e; k += 4) {
        int2 p[4];
#pragma unroll
        for (int q = 0; q < 4; q++) p[q] = __ldg(ew + k + q);
        half2 v[4];
#pragma unroll
        for (int q = 0; q < 4; q++) v[q] = __ldg(hb + (size_t)p[q].x * 32 + lane);
#pragma unroll
        for (int q = 0; q < 4; q++) {
            float wq = __int_as_float(p[q].y);
            float2 f = __half22float2(v[q]);
            if (q & 1) { a1x += f.x * wq; a1y += f.y * wq; }
            else       { a0x += f.x * wq; a0y += f.y * wq; }
        }
    }
    for (; k < e; k++) {
        int2 p0 = __ldg(ew + k);
        float w0 = __int_as_float(p0.y);
        float2 f = __half22float2(__ldg(hb + (size_t)p0.x * 32 + lane));
        a0x += f.x * w0; a0y += f.y * w0;
    }

    float2 bv = __ldg((const float2*)bias + lane);
    a0x += a1x + bv.x;
    a0y += a1y + bv.y;
    *((float2*)(out + (size_t)node * 64) + lane) = make_float2(a0x, a0y);
}

// ---------------- launch ----------------

extern "C" void kernel_launch(void* const* d_in, const int* in_sizes, int n_in,
                              void* d_out, int out_size) {
    const float* x  = (const float*)d_in[0];
    const int*   ei = (const int*)d_in[1];      // int32 (JAX x64 disabled)
    const float* W1 = (const float*)d_in[2];
    const float* b1 = (const float*)d_in[3];
    const float* W2 = (const float*)d_in[4];
    const float* b2 = (const float*)d_in[5];
    const float* W3 = (const float*)d_in[6];
    const float* b3 = (const float*)d_in[7];
    float* out = (float*)d_out;

    const int N = in_sizes[0] / 128;
    const int E = in_sizes[1] / 2;
    const int* row = ei;
    const int* col = ei + E;

    int *deg, *start, *cursor, *bsums;
    int2* ew;
    float* dinv;
    __half *x16, *h, *act, *w1t, *w2t, *w3t;
    cudaGetSymbolAddress((void**)&deg,    g_deg);
    cudaGetSymbolAddress((void**)&dinv,   g_dinv);
    cudaGetSymbolAddress((void**)&start,  g_start);
    cudaGetSymbolAddress((void**)&cursor, g_cursor);
    cudaGetSymbolAddress((void**)&bsums,  g_bsums);
    cudaGetSymbolAddress((void**)&ew,     g_ew);
    cudaGetSymbolAddress((void**)&x16,    g_x16);
    cudaGetSymbolAddress((void**)&h,      g_h);
    cudaGetSymbolAddress((void**)&act,    g_act);
    cudaGetSymbolAddress((void**)&w1t,    g_w1t);
    cudaGetSymbolAddress((void**)&w2t,    g_w2t);
    cudaGetSymbolAddress((void**)&w3t,    g_w3t);

    const int SMEM128 = (64 * XP + 128 * WP) * 2;    // 52224 B
    const int SMEM64  = (128 * XP + 128 * WP) * 2;   // 69632 B
    cudaFuncSetAttribute(gemm_k<128>, cudaFuncAttributeMaxDynamicSharedMemorySize, SMEM128);
    cudaFuncSetAttribute(gemm_k<64>,  cudaFuncAttributeMaxDynamicSharedMemorySize, SMEM64);

    const int TB = 256;
    const int gN    = (N + TB - 1) / TB;
    const int gE    = (E + TB - 1) / TB;
    const int gW    = ((size_t)N * 32 + TB - 1) / TB;  // warp-per-node grid
    const int gG128 = (N + 63) / 64;                   // 64-row tiles
    const int gG64  = (N + 127) / 128;                 // 128-row tiles
    const int gP    = (PREP_TOTAL + TB - 1) / TB;      // fused prep
    const int nb    = (N + SCAN_B - 1) / SCAN_B;       // 98

    // gemm1 at launch index 3 (ncu samples there)
    prep_k<<<gP, TB>>>(x, W1, W2, W3, deg, w1t, w2t, w3t, (uint2*)x16); // 0
    degree_k<<<gE, TB>>>(col, deg, E);                               // 1
    scan1_dinv_k<<<nb, SCAN_B>>>(deg, start, bsums, dinv, N);        // 2
    gemm_k<128><<<gG128, TB, SMEM128>>>(x16, w1t, h, N);             // 3 <- profiled
    scan2_k<<<1, MAX_BLOCKS>>>(bsums, nb);                           // 4
    scan3_cursor_k<<<gN, TB>>>(start, bsums, cursor, N);             // 5
    fill_k<<<gE, TB>>>(row, col, dinv, cursor, ew, E);               // 6

    // ---- layer 1 ----
    agg128_k<<<gW, TB>>>(h, ew, start, b1, act, N);                  // 7
    // ---- layer 2 ----
    gemm_k<128><<<gG128, TB, SMEM128>>>(act, w2t, h, N);             // 8
    agg128_k<<<gW, TB>>>(h, ew, start, b2, act, N);                  // 9
    // ---- layer 3 ----
    gemm_k<64><<<gG64, TB, SMEM64>>>(act, w3t, h, N);                // 10
    agg64_k<<<gW, TB>>>(h, ew, start, b3, out, N);                   // 11
}

// round 16
// speedup vs baseline: 1.1510x; 1.0157x over previous
#include <cuda_runtime.h>
#include <cuda_fp16.h>
#include <cstdint>

// Problem constants (fixed by the dataset)
#define NN 100000
#define EE 1600000
#define SCAN_B 1024
#define MAX_BLOCKS 128   // ceil(NN/1024) = 98 <= 128

// Scratch (no cudaMalloc allowed)
__device__ int   g_deg[NN];
__device__ __align__(16) float g_dinv[NN];
__device__ int   g_start[NN + 1];
__device__ int   g_cursor[NN];
__device__ int   g_bsums[MAX_BLOCKS];
__device__ __align__(16) int2   g_ew[EE];                   // packed {srcrow, w bits}
__device__ __align__(16) __half g_x16[(size_t)NN * 128];    // fp16 copy of input x
__device__ __align__(16) __half g_h[(size_t)NN * 128];      // GEMM output (fp16)
__device__ __align__(16) __half g_act[(size_t)NN * 128];    // inter-layer activations (fp16)
__device__ __align__(16) __half g_w1t[128 * 128];           // W1 fp16 row-major
__device__ __align__(16) __half g_w2t[128 * 128];           // W2 fp16
__device__ __align__(16) __half g_w3t[128 * 64];            // W3 fp16

// ---------------- fused prep: zero deg + W1/W2/W3 fp16 + x fp16 ----------------

#define PREP_W1 (NN)
#define PREP_W2 (PREP_W1 + 128 * 128)
#define PREP_W3 (PREP_W2 + 128 * 128)
#define PREP_X  (PREP_W3 + 128 * 64)
#define PREP_TOTAL (PREP_X + NN * 32)

__global__ void prep_k(const float* __restrict__ x, const float* __restrict__ W1,
                       const float* __restrict__ W2, const float* __restrict__ W3,
                       int* __restrict__ deg, __half* __restrict__ w1t,
                       __half* __restrict__ w2t, __half* __restrict__ w3t,
                       uint2* __restrict__ x16) {
    int i = blockIdx.x * blockDim.x + threadIdx.x;
    if (i < PREP_W1) {
        deg[i] = 0;
    } else if (i < PREP_W2) {
        int j = i - PREP_W1;
        w1t[j] = __float2half_rn(W1[j]);
    } else if (i < PREP_W3) {
        int j = i - PREP_W2;
        w2t[j] = __float2half_rn(W2[j]);
    } else if (i < PREP_X) {
        int j = i - PREP_W3;
        w3t[j] = __float2half_rn(W3[j]);
    } else if (i < PREP_TOTAL) {
        int j = i - PREP_X;
        float4 f = __ldg((const float4*)x + j);
        half2 a = __floats2half2_rn(f.x, f.y);
        half2 b = __floats2half2_rn(f.z, f.w);
        uint2 o;
        o.x = *(const uint32_t*)&a;
        o.y = *(const uint32_t*)&b;
        x16[j] = o;
    }
}

__global__ void degree_k(const int* __restrict__ col, int* __restrict__ deg, int E) {
    int e = blockIdx.x * blockDim.x + threadIdx.x;
    if (e < E) atomicAdd(&deg[col[e]], 1);
}

__global__ void scan1_dinv_k(const int* __restrict__ deg, int* __restrict__ start,
                             int* __restrict__ bsums, float* __restrict__ dinv, int n) {
    __shared__ int s[SCAN_B];
    int i = blockIdx.x * SCAN_B + threadIdx.x;
    int v = (i < n) ? deg[i] : 0;
    if (i < n) dinv[i] = (v > 0) ? rsqrtf((float)v) : 0.0f;
    s[threadIdx.x] = v;
    __syncthreads();
    for (int off = 1; off < SCAN_B; off <<= 1) {
        int t = (threadIdx.x >= off) ? s[threadIdx.x - off] : 0;
        __syncthreads();
        s[threadIdx.x] += t;
        __syncthreads();
    }
    if (i < n) start[i + 1] = s[threadIdx.x];
    if (threadIdx.x == SCAN_B - 1) bsums[blockIdx.x] = s[SCAN_B - 1];
}

__global__ void scan2_k(int* __restrict__ bsums, int nb) {
    __shared__ int s[MAX_BLOCKS];
    int v = (threadIdx.x < nb) ? bsums[threadIdx.x] : 0;
    s[threadIdx.x] = v;
    __syncthreads();
    for (int off = 1; off < MAX_BLOCKS; off <<= 1) {
        int t = (threadIdx.x >= off) ? s[threadIdx.x - off] : 0;
        __syncthreads();
        s[threadIdx.x] += t;
        __syncthreads();
    }
    if (threadIdx.x < nb) bsums[threadIdx.x] = s[threadIdx.x] - v;  // exclusive
}

__global__ void scan3_cursor_k(int* __restrict__ start, const int* __restrict__ bsums,
                               int* __restrict__ cursor, int n) {
    int i = blockIdx.x * blockDim.x + threadIdx.x;
    if (i < n) {
        int v = start[i + 1] + bsums[i >> 10];
        start[i + 1] = v;
        if (i + 1 < n) cursor[i + 1] = v;
        if (i == 0) { start[0] = 0; cursor[0] = 0; }
    }
}

__global__ void fill_k(const int* __restrict__ row, const int* __restrict__ col,
                       const float* __restrict__ dinv, int* __restrict__ cursor,
                       int2* __restrict__ ew, int E) {
    int e = blockIdx.x * blockDim.x + threadIdx.x;
    if (e < E) {
        int r = row[e];
        int c = col[e];
        int pos = atomicAdd(&cursor[c], 1);
        ew[pos] = make_int2(r, __float_as_int(dinv[r] * dinv[c]));
    }
}

// ---------------- tensor-core GEMM (mma.sync fallback HMMA) ---------------------

__device__ __forceinline__ uint32_t smem_u32(const void* p) {
    uint32_t a;
    asm("{ .reg .u64 t; cvta.to.shared.u64 t, %1; cvt.u32.u64 %0, t; }" : "=r"(a) : "l"(p));
    return a;
}

__device__ __forceinline__ void cp_async16(uint32_t dst, const void* src, uint32_t sz) {
    asm volatile("cp.async.cg.shared.global [%0], [%1], 16, %2;"
                 :: "r"(dst), "l"(src), "r"(sz) : "memory");
}

__device__ __forceinline__ void cp_async_wait_all() {
    asm volatile("cp.async.commit_group;\n\tcp.async.wait_group 0;" ::: "memory");
}

__device__ __forceinline__ void mma16816(float* c,
    uint32_t a0, uint32_t a1, uint32_t a2, uint32_t a3,
    uint32_t b0, uint32_t b1) {
    asm volatile(
        "mma.sync.aligned.m16n8k16.row.col.f32.f16.f16.f32 "
        "{%0,%1,%2,%3}, {%4,%5,%6,%7}, {%8,%9}, {%0,%1,%2,%3};"
        : "+f"(c[0]), "+f"(c[1]), "+f"(c[2]), "+f"(c[3])
        : "r"(a0), "r"(a1), "r"(a2), "r"(a3), "r"(b0), "r"(b1));
}

__device__ __forceinline__ void ldsm_x4(uint32_t addr, uint32_t& r0, uint32_t& r1,
                                        uint32_t& r2, uint32_t& r3) {
    asm volatile("ldmatrix.sync.aligned.m8n8.x4.shared.b16 {%0,%1,%2,%3}, [%4];"
                 : "=r"(r0), "=r"(r1), "=r"(r2), "=r"(r3) : "r"(addr));
}

__device__ __forceinline__ void ldsm_x4_t(uint32_t addr, uint32_t& r0, uint32_t& r1,
                                          uint32_t& r2, uint32_t& r3) {
    asm volatile("ldmatrix.sync.aligned.m8n8.x4.trans.shared.b16 {%0,%1,%2,%3}, [%4];"
                 : "=r"(r0), "=r"(r1), "=r"(r2), "=r"(r3) : "r"(addr));
}

#define XP 136
#define WP 136

template <int FOUT>
__global__ __launch_bounds__(256, 3)
void gemm_k(const __half* __restrict__ X, const __half* __restrict__ Wt,
            __half* __restrict__ H, int n) {
    constexpr int TM = (FOUT == 128) ? 64 : 128;  // rows per block
    constexpr int NW = FOUT / 64;                 // warps along N (2 or 1)

    extern __shared__ __half smh[];
    __half* Xh  = smh;               // TM x XP
    __half* Wsm = smh + TM * XP;     // 128 x WP, row-major [k][c]

    const int tid  = threadIdx.x;
    const int warp = tid >> 5;
    const int lane = tid & 31;
    const int g = lane >> 2;       // 0..7
    const int t = lane & 3;        // 0..3
    const int row0 = blockIdx.x * TM;

    const uint32_t xh_base = smem_u32(Xh);
    const uint32_t wm_base = smem_u32(Wsm);

    // X fill via cp.async: TM*16 chunks of 16B
#pragma unroll
    for (int u = tid; u < TM * 16; u += 256) {
        int r = u >> 4, m = u & 15;
        bool ok = (row0 + r < n);
        const __half* src = X + (size_t)(ok ? (row0 + r) : 0) * 128 + m * 8;
        cp_async16(xh_base + (r * XP + m * 8) * 2, src, ok ? 16u : 0u);
    }
    // W fill via cp.async
#pragma unroll
    for (int u = tid; u < 128 * (FOUT / 8); u += 256) {
        int k = u / (FOUT / 8), c8 = (u % (FOUT / 8)) * 8;
        cp_async16(wm_base + (k * WP + c8) * 2, Wt + k * FOUT + c8, 16u);
    }
    cp_async_wait_all();
    __syncthreads();

    const int wm = (warp / NW) * 16;      // warp row base
    const int n0 = (warp % NW) * 64;      // warp col base

    const int lrow = lane & 15;
    const int lk8  = ((lane >> 4) & 1) * 8;
    uint32_t xa_base = xh_base + ((wm + lrow) * XP + lk8) * 2;
    uint32_t wb_base = wm_base + (lrow * WP + n0 + lk8) * 2;

    float acc[8][4];
#pragma unroll
    for (int j = 0; j < 8; j++)
        acc[j][0] = acc[j][1] = acc[j][2] = acc[j][3] = 0.f;

#pragma unroll
    for (int ks = 0; ks < 8; ks++) {
        const int k0 = ks * 16;
        uint32_t a0, a1, a2, a3;
        ldsm_x4(xa_base + k0 * 2, a0, a1, a2, a3);
#pragma unroll
        for (int jp = 0; jp < 4; jp++) {
            uint32_t b0, b1, b2, b3;
            ldsm_x4_t(wb_base + (k0 * WP + jp * 16) * 2, b0, b1, b2, b3);
            mma16816(acc[2 * jp],     a0, a1, a2, a3, b0, b1);
            mma16816(acc[2 * jp + 1], a0, a1, a2, a3, b2, b3);
        }
    }

    // epilogue: c0,c1 -> (row wm+g, col n0+8j+2t); c2,c3 -> row +8
    const int r0i = row0 + wm + g;
#pragma unroll
    for (int j = 0; j < 8; j++) {
        int cidx = n0 + j * 8 + 2 * t;
        if (r0i < n)
            *(half2*)(H + (size_t)r0i * FOUT + cidx) =
                __floats2half2_rn(acc[j][0], acc[j][1]);
        if (r0i + 8 < n)
            *(half2*)(H + (size_t)(r0i + 8) * FOUT + cidx) =
                __floats2half2_rn(acc[j][2], acc[j][3]);
    }
}

// ---------------- aggregate (fp16 gather, fp32 accumulate, MLP=8) ----------------

__global__ void agg128_k(const __half* __restrict__ h, const int2* __restrict__ ew,
                         const int* __restrict__ start, const float* __restrict__ bias,
                         __half* __restrict__ out, int n) {
    int node = (blockIdx.x * blockDim.x + threadIdx.x) >> 5;
    int lane = threadIdx.x & 31;
    if (node >= n) return;

    int s = start[node];
    int e = start[node + 1];
    const uint2* hb = (const uint2*)h;   // 8B = 4 halves per lane; row = 32 uint2

    float a0x = 0.f, a0y = 0.f, a0z = 0.f, a0w = 0.f;
    float a1x = 0.f, a1y = 0.f, a1z = 0.f, a1w = 0.f;

    int k = s;
    for (; k + 8 <= e; k += 8) {
        int2 p[8];
#pragma unroll
        for (int q = 0; q < 8; q++) p[q] = __ldg(ew + k + q);
        uint2 v[8];
#pragma unroll
        for (int q = 0; q < 8; q++) v[q] = __ldg(hb + (size_t)p[q].x * 32 + lane);
#pragma unroll
        for (int q = 0; q < 8; q++) {
            float wq = __int_as_float(p[q].y);
            float2 f0 = __half22float2(*(const half2*)&v[q].x);
            float2 f1 = __half22float2(*(const half2*)&v[q].y);
            if (q & 1) {
                a1x += f0.x * wq; a1y += f0.y * wq;
                a1z += f1.x * wq; a1w += f1.y * wq;
            } else {
                a0x += f0.x * wq; a0y += f0.y * wq;
                a0z += f1.x * wq; a0w += f1.y * wq;
            }
        }
    }
    for (; k + 4 <= e; k += 4) {
        int2 p[4];
#pragma unroll
        for (int q = 0; q < 4; q++) p[q] = __ldg(ew + k + q);
        uint2 v[4];
#pragma unroll
        for (int q = 0; q < 4; q++) v[q] = __ldg(hb + (size_t)p[q].x * 32 + lane);
#pragma unroll
        for (int q = 0; q < 4; q++) {
            float wq = __int_as_float(p[q].y);
            float2 f0 = __half22float2(*(const half2*)&v[q].x);
            float2 f1 = __half22float2(*(const half2*)&v[q].y);
            if (q & 1) {
                a1x += f0.x * wq; a1y += f0.y * wq;
                a1z += f1.x * wq; a1w += f1.y * wq;
            } else {
                a0x += f0.x * wq; a0y += f0.y * wq;
                a0z += f1.x * wq; a0w += f1.y * wq;
            }
        }
    }
    for (; k < e; k++) {
        int2 p0 = __ldg(ew + k);
        float w0 = __int_as_float(p0.y);
        uint2 v0 = __ldg(hb + (size_t)p0.x * 32 + lane);
        float2 f0 = __half22float2(*(const half2*)&v0.x);
        float2 f1 = __half22float2(*(const half2*)&v0.y);
        a0x += f0.x * w0; a0y += f0.y * w0;
        a0z += f1.x * w0; a0w += f1.y * w0;
    }

    float4 bv = __ldg((const float4*)bias + lane);
    a0x = fmaxf(a0x + a1x + bv.x, 0.f);
    a0y = fmaxf(a0y + a1y + bv.y, 0.f);
    a0z = fmaxf(a0z + a1z + bv.z, 0.f);
    a0w = fmaxf(a0w + a1w + bv.w, 0.f);

    half2 o0 = __floats2half2_rn(a0x, a0y);
    half2 o1 = __floats2half2_rn(a0z, a0w);
    uint2 ov;
    ov.x = *(const uint32_t*)&o0;
    ov.y = *(const uint32_t*)&o1;
    *((uint2*)out + (size_t)node * 32 + lane) = ov;
}

__global__ void agg64_k(const __half* __restrict__ h, const int2* __restrict__ ew,
                        const int* __restrict__ start, const float* __restrict__ bias,
                        float* __restrict__ out, int n) {
    int node = (blockIdx.x * blockDim.x + threadIdx.x) >> 5;
    int lane = threadIdx.x & 31;
    if (node >= n) return;

    int s = start[node];
    int e = start[node + 1];
    const half2* hb = (const half2*)h;   // row = 32 half2

    float a0x = 0.f, a0y = 0.f, a1x = 0.f, a1y = 0.f;

    int k = s;
    for (; k + 8 <= e; k += 8) {
        int2 p[8];
#pragma unroll
        for (int q = 0; q < 8; q++) p[q] = __ldg(ew + k + q);
        half2 v[8];
#pragma unroll
        for (int q = 0; q < 8; q++) v[q] = __ldg(hb + (size_t)p[q].x * 32 + lane);
#pragma unroll
        for (int q = 0; q < 8; q++) {
            float wq = __int_as_float(p[q].y);
            float2 f = __half22float2(v[q]);
            if (q & 1) { a1x += f.x * wq; a1y += f.y * wq; }
            else       { a0x += f.x * wq; a0y += f.y * wq; }
        }
    }
    for (; k + 4 <= e; k += 4) {
        int2 p[4];
#pragma unroll
        for (int q = 0; q < 4; q++) p[q] = __ldg(ew + k + q);
        half2 v[4];
#pragma unroll
        for (int q = 0; q < 4; q++) v[q] = __ldg(hb + (size_t)p[q].x * 32 + lane);
#pragma unroll
        for (int q = 0; q < 4; q++) {
            float wq = __int_as_float(p[q].y);
            float2 f = __half22float2(v[q]);
            if (q & 1) { a1x += f.x * wq; a1y += f.y * wq; }
            else       { a0x += f.x * wq; a0y += f.y * wq; }
        }
    }
    for (; k < e; k++) {
        int2 p0 = __ldg(ew + k);
        float w0 = __int_as_float(p0.y);
        float2 f = __half22float2(__ldg(hb + (size_t)p0.x * 32 + lane));
        a0x += f.x * w0; a0y += f.y * w0;
    }

    float2 bv = __ldg((const float2*)bias + lane);
    a0x += a1x + bv.x;
    a0y += a1y + bv.y;
    *((float2*)(out + (size_t)node * 64) + lane) = make_float2(a0x, a0y);
}

// ---------------- launch ----------------

extern "C" void kernel_launch(void* const* d_in, const int* in_sizes, int n_in,
                              void* d_out, int out_size) {
    const float* x  = (const float*)d_in[0];
    const int*   ei = (const int*)d_in[1];      // int32 (JAX x64 disabled)
    const float* W1 = (const float*)d_in[2];
    const float* b1 = (const float*)d_in[3];
    const float* W2 = (const float*)d_in[4];
    const float* b2 = (const float*)d_in[5];
    const float* W3 = (const float*)d_in[6];
    const float* b3 = (const float*)d_in[7];
    float* out = (float*)d_out;

    const int N = in_sizes[0] / 128;
    const int E = in_sizes[1] / 2;
    const int* row = ei;
    const int* col = ei + E;

    int *deg, *start, *cursor, *bsums;
    int2* ew;
    float* dinv;
    __half *x16, *h, *act, *w1t, *w2t, *w3t;
    cudaGetSymbolAddress((void**)&deg,    g_deg);
    cudaGetSymbolAddress((void**)&dinv,   g_dinv);
    cudaGetSymbolAddress((void**)&start,  g_start);
    cudaGetSymbolAddress((void**)&cursor, g_cursor);
    cudaGetSymbolAddress((void**)&bsums,  g_bsums);
    cudaGetSymbolAddress((void**)&ew,     g_ew);
    cudaGetSymbolAddress((void**)&x16,    g_x16);
    cudaGetSymbolAddress((void**)&h,      g_h);
    cudaGetSymbolAddress((void**)&act,    g_act);
    cudaGetSymbolAddress((void**)&w1t,    g_w1t);
    cudaGetSymbolAddress((void**)&w2t,    g_w2t);
    cudaGetSymbolAddress((void**)&w3t,    g_w3t);

    const int SMEM128 = (64 * XP + 128 * WP) * 2;    // 52224 B
    const int SMEM64  = (128 * XP + 128 * WP) * 2;   // 69632 B
    cudaFuncSetAttribute(gemm_k<128>, cudaFuncAttributeMaxDynamicSharedMemorySize, SMEM128);
    cudaFuncSetAttribute(gemm_k<64>,  cudaFuncAttributeMaxDynamicSharedMemorySize, SMEM64);

    const int TB = 256;
    const int gN    = (N + TB - 1) / TB;
    const int gE    = (E + TB - 1) / TB;
    const int gW    = ((size_t)N * 32 + TB - 1) / TB;  // warp-per-node grid
    const int gG128 = (N + 63) / 64;                   // 64-row tiles
    const int gG64  = (N + 127) / 128;                 // 128-row tiles
    const int gP    = (PREP_TOTAL + TB - 1) / TB;      // fused prep
    const int nb    = (N + SCAN_B - 1) / SCAN_B;       // 98

    // gemm1 at launch index 3 (ncu samples there)
    prep_k<<<gP, TB>>>(x, W1, W2, W3, deg, w1t, w2t, w3t, (uint2*)x16); // 0
    degree_k<<<gE, TB>>>(col, deg, E);                               // 1
    scan1_dinv_k<<<nb, SCAN_B>>>(deg, start, bsums, dinv, N);        // 2
    gemm_k<128><<<gG128, TB, SMEM128>>>(x16, w1t, h, N);             // 3 <- profiled
    scan2_k<<<1, MAX_BLOCKS>>>(bsums, nb);                           // 4
    scan3_cursor_k<<<gN, TB>>>(start, bsums, cursor, N);             // 5
    fill_k<<<gE, TB>>>(row, col, dinv, cursor, ew, E);               // 6

    // ---- layer 1 ----
    agg128_k<<<gW, TB>>>(h, ew, start, b1, act, N);                  // 7
    // ---- layer 2 ----
    gemm_k<128><<<gG128, TB, SMEM128>>>(act, w2t, h, N);             // 8
    agg128_k<<<gW, TB>>>(h, ew, start, b2, act, N);                  // 9
    // ---- layer 3 ----
    gemm_k<64><<<gG64, TB, SMEM64>>>(act, w3t, h, N);                // 10
    agg64_k<<<gW, TB>>>(h, ew, start, b3, out, N);                   // 11
}

// round 17
// speedup vs baseline: 1.1810x; 1.0260x over previous
#include <cuda_runtime.h>
#include <cuda_fp16.h>
#include <cstdint>

// Problem constants (fixed by the dataset)
#define NN 100000
#define EE 1600000
#define SCAN_B 1024
#define MAX_BLOCKS 128   // ceil(NN/1024) = 98 <= 128

// Scratch (no cudaMalloc allowed)
__device__ int   g_deg[NN];
__device__ __align__(16) float g_dinv[NN];
__device__ int   g_start[NN + 1];
__device__ int   g_cursor[NN];
__device__ int   g_bsums[MAX_BLOCKS];
__device__ __align__(16) int2   g_ew[EE];                   // packed {srcrow, w bits}
__device__ __align__(16) __half g_x16[(size_t)NN * 128];    // fp16 copy of input x
__device__ __align__(16) __half g_h[(size_t)NN * 128];      // GEMM output (fp16)
__device__ __align__(16) __half g_act[(size_t)NN * 128];    // inter-layer activations (fp16)
__device__ __align__(16) __half g_w1t[128 * 128];           // W1 fp16 row-major
__device__ __align__(16) __half g_w2t[128 * 128];           // W2 fp16
__device__ __align__(16) __half g_w3t[128 * 64];            // W3 fp16

// ---------------- prep (branch A): W1/W2/W3 fp16 + x fp16 ----------------

#define PREP_W2 (128 * 128)
#define PREP_W3 (PREP_W2 + 128 * 128)
#define PREP_X  (PREP_W3 + 128 * 64)
#define PREP_TOTAL (PREP_X + NN * 32)

__global__ void prep_k(const float* __restrict__ x, const float* __restrict__ W1,
                       const float* __restrict__ W2, const float* __restrict__ W3,
                       __half* __restrict__ w1t, __half* __restrict__ w2t,
                       __half* __restrict__ w3t, uint2* __restrict__ x16) {
    int i = blockIdx.x * blockDim.x + threadIdx.x;
    if (i < PREP_W2) {
        w1t[i] = __float2half_rn(W1[i]);
    } else if (i < PREP_W3) {
        int j = i - PREP_W2;
        w2t[j] = __float2half_rn(W2[j]);
    } else if (i < PREP_X) {
        int j = i - PREP_W3;
        w3t[j] = __float2half_rn(W3[j]);
    } else if (i < PREP_TOTAL) {
        int j = i - PREP_X;
        float4 f = __ldg((const float4*)x + j);
        half2 a = __floats2half2_rn(f.x, f.y);
        half2 b = __floats2half2_rn(f.z, f.w);
        uint2 o;
        o.x = *(const uint32_t*)&a;
        o.y = *(const uint32_t*)&b;
        x16[j] = o;
    }
}

// ---------------- CSC build (branch B) ----------------

__global__ void zero_deg_k(int* __restrict__ p, int n) {
    int i = blockIdx.x * blockDim.x + threadIdx.x;
    if (i < n) p[i] = 0;
}

__global__ void degree_k(const int* __restrict__ col, int* __restrict__ deg, int E) {
    int e = blockIdx.x * blockDim.x + threadIdx.x;
    if (e < E) atomicAdd(&deg[col[e]], 1);
}

__global__ void scan1_dinv_k(const int* __restrict__ deg, int* __restrict__ start,
                             int* __restrict__ bsums, float* __restrict__ dinv, int n) {
    __shared__ int s[SCAN_B];
    int i = blockIdx.x * SCAN_B + threadIdx.x;
    int v = (i < n) ? deg[i] : 0;
    if (i < n) dinv[i] = (v > 0) ? rsqrtf((float)v) : 0.0f;
    s[threadIdx.x] = v;
    __syncthreads();
    for (int off = 1; off < SCAN_B; off <<= 1) {
        int t = (threadIdx.x >= off) ? s[threadIdx.x - off] : 0;
        __syncthreads();
        s[threadIdx.x] += t;
        __syncthreads();
    }
    if (i < n) start[i + 1] = s[threadIdx.x];
    if (threadIdx.x == SCAN_B - 1) bsums[blockIdx.x] = s[SCAN_B - 1];
}

__global__ void scan2_k(int* __restrict__ bsums, int nb) {
    __shared__ int s[MAX_BLOCKS];
    int v = (threadIdx.x < nb) ? bsums[threadIdx.x] : 0;
    s[threadIdx.x] = v;
    __syncthreads();
    for (int off = 1; off < MAX_BLOCKS; off <<= 1) {
        int t = (threadIdx.x >= off) ? s[threadIdx.x - off] : 0;
        __syncthreads();
        s[threadIdx.x] += t;
        __syncthreads();
    }
    if (threadIdx.x < nb) bsums[threadIdx.x] = s[threadIdx.x] - v;  // exclusive
}

__global__ void scan3_cursor_k(int* __restrict__ start, const int* __restrict__ bsums,
                               int* __restrict__ cursor, int n) {
    int i = blockIdx.x * blockDim.x + threadIdx.x;
    if (i < n) {
        int v = start[i + 1] + bsums[i >> 10];
        start[i + 1] = v;
        if (i + 1 < n) cursor[i + 1] = v;
        if (i == 0) { start[0] = 0; cursor[0] = 0; }
    }
}

__global__ void fill_k(const int* __restrict__ row, const int* __restrict__ col,
                       const float* __restrict__ dinv, int* __restrict__ cursor,
                       int2* __restrict__ ew, int E) {
    int e = blockIdx.x * blockDim.x + threadIdx.x;
    if (e < E) {
        int r = row[e];
        int c = col[e];
        int pos = atomicAdd(&cursor[c], 1);
        ew[pos] = make_int2(r, __float_as_int(dinv[r] * dinv[c]));
    }
}

// ---------------- tensor-core GEMM (mma.sync fallback HMMA) ---------------------

__device__ __forceinline__ uint32_t smem_u32(const void* p) {
    uint32_t a;
    asm("{ .reg .u64 t; cvta.to.shared.u64 t, %1; cvt.u32.u64 %0, t; }" : "=r"(a) : "l"(p));
    return a;
}

__device__ __forceinline__ void cp_async16(uint32_t dst, const void* src, uint32_t sz) {
    asm volatile("cp.async.cg.shared.global [%0], [%1], 16, %2;"
                 :: "r"(dst), "l"(src), "r"(sz) : "memory");
}

__device__ __forceinline__ void cp_async_wait_all() {
    asm volatile("cp.async.commit_group;\n\tcp.async.wait_group 0;" ::: "memory");
}

__device__ __forceinline__ void mma16816(float* c,
    uint32_t a0, uint32_t a1, uint32_t a2, uint32_t a3,
    uint32_t b0, uint32_t b1) {
    asm volatile(
        "mma.sync.aligned.m16n8k16.row.col.f32.f16.f16.f32 "
        "{%0,%1,%2,%3}, {%4,%5,%6,%7}, {%8,%9}, {%0,%1,%2,%3};"
        : "+f"(c[0]), "+f"(c[1]), "+f"(c[2]), "+f"(c[3])
        : "r"(a0), "r"(a1), "r"(a2), "r"(a3), "r"(b0), "r"(b1));
}

__device__ __forceinline__ void ldsm_x4(uint32_t addr, uint32_t& r0, uint32_t& r1,
                                        uint32_t& r2, uint32_t& r3) {
    asm volatile("ldmatrix.sync.aligned.m8n8.x4.shared.b16 {%0,%1,%2,%3}, [%4];"
                 : "=r"(r0), "=r"(r1), "=r"(r2), "=r"(r3) : "r"(addr));
}

__device__ __forceinline__ void ldsm_x4_t(uint32_t addr, uint32_t& r0, uint32_t& r1,
                                          uint32_t& r2, uint32_t& r3) {
    asm volatile("ldmatrix.sync.aligned.m8n8.x4.trans.shared.b16 {%0,%1,%2,%3}, [%4];"
                 : "=r"(r0), "=r"(r1), "=r"(r2), "=r"(r3) : "r"(addr));
}

#define XP 136
#define WP 136

template <int FOUT>
__global__ __launch_bounds__(256, 3)
void gemm_k(const __half* __restrict__ X, const __half* __restrict__ Wt,
            __half* __restrict__ H, int n) {
    constexpr int TM = (FOUT == 128) ? 64 : 128;  // rows per block
    constexpr int NW = FOUT / 64;                 // warps along N (2 or 1)

    extern __shared__ __half smh[];
    __half* Xh  = smh;               // TM x XP
    __half* Wsm = smh + TM * XP;     // 128 x WP, row-major [k][c]

    const int tid  = threadIdx.x;
    const int warp = tid >> 5;
    const int lane = tid & 31;
    const int g = lane >> 2;       // 0..7
    const int t = lane & 3;        // 0..3
    const int row0 = blockIdx.x * TM;

    const uint32_t xh_base = smem_u32(Xh);
    const uint32_t wm_base = smem_u32(Wsm);

    // X fill via cp.async: TM*16 chunks of 16B
#pragma unroll
    for (int u = tid; u < TM * 16; u += 256) {
        int r = u >> 4, m = u & 15;
        bool ok = (row0 + r < n);
        const __half* src = X + (size_t)(ok ? (row0 + r) : 0) * 128 + m * 8;
        cp_async16(xh_base + (r * XP + m * 8) * 2, src, ok ? 16u : 0u);
    }
    // W fill via cp.async
#pragma unroll
    for (int u = tid; u < 128 * (FOUT / 8); u += 256) {
        int k = u / (FOUT / 8), c8 = (u % (FOUT / 8)) * 8;
        cp_async16(wm_base + (k * WP + c8) * 2, Wt + k * FOUT + c8, 16u);
    }
    cp_async_wait_all();
    __syncthreads();

    const int wm = (warp / NW) * 16;      // warp row base
    const int n0 = (warp % NW) * 64;      // warp col base

    const int lrow = lane & 15;
    const int lk8  = ((lane >> 4) & 1) * 8;
    uint32_t xa_base = xh_base + ((wm + lrow) * XP + lk8) * 2;
    uint32_t wb_base = wm_base + (lrow * WP + n0 + lk8) * 2;

    float acc[8][4];
#pragma unroll
    for (int j = 0; j < 8; j++)
        acc[j][0] = acc[j][1] = acc[j][2] = acc[j][3] = 0.f;

#pragma unroll
    for (int ks = 0; ks < 8; ks++) {
        const int k0 = ks * 16;
        uint32_t a0, a1, a2, a3;
        ldsm_x4(xa_base + k0 * 2, a0, a1, a2, a3);
#pragma unroll
        for (int jp = 0; jp < 4; jp++) {
            uint32_t b0, b1, b2, b3;
            ldsm_x4_t(wb_base + (k0 * WP + jp * 16) * 2, b0, b1, b2, b3);
            mma16816(acc[2 * jp],     a0, a1, a2, a3, b0, b1);
            mma16816(acc[2 * jp + 1], a0, a1, a2, a3, b2, b3);
        }
    }

    // epilogue: c0,c1 -> (row wm+g, col n0+8j+2t); c2,c3 -> row +8
    const int r0i = row0 + wm + g;
#pragma unroll
    for (int j = 0; j < 8; j++) {
        int cidx = n0 + j * 8 + 2 * t;
        if (r0i < n)
            *(half2*)(H + (size_t)r0i * FOUT + cidx) =
                __floats2half2_rn(acc[j][0], acc[j][1]);
        if (r0i + 8 < n)
            *(half2*)(H + (size_t)(r0i + 8) * FOUT + cidx) =
                __floats2half2_rn(acc[j][2], acc[j][3]);
    }
}

// ---------------- aggregate (fp16 gather, fp32 accumulate, MLP=8) ----------------

__global__ void agg128_k(const __half* __restrict__ h, const int2* __restrict__ ew,
                         const int* __restrict__ start, const float* __restrict__ bias,
                         __half* __restrict__ out, int n) {
    int node = (blockIdx.x * blockDim.x + threadIdx.x) >> 5;
    int lane = threadIdx.x & 31;
    if (node >= n) return;

    int s = start[node];
    int e = start[node + 1];
    const uint2* hb = (const uint2*)h;   // 8B = 4 halves per lane; row = 32 uint2

    float a0x = 0.f, a0y = 0.f, a0z = 0.f, a0w = 0.f;
    float a1x = 0.f, a1y = 0.f, a1z = 0.f, a1w = 0.f;

    int k = s;
    for (; k + 8 <= e; k += 8) {
        int2 p[8];
#pragma unroll
        for (int q = 0; q < 8; q++) p[q] = __ldg(ew + k + q);
        uint2 v[8];
#pragma unroll
        for (int q = 0; q < 8; q++) v[q] = __ldg(hb + (size_t)p[q].x * 32 + lane);
#pragma unroll
        for (int q = 0; q < 8; q++) {
            float wq = __int_as_float(p[q].y);
            float2 f0 = __half22float2(*(const half2*)&v[q].x);
            float2 f1 = __half22float2(*(const half2*)&v[q].y);
            if (q & 1) {
                a1x += f0.x * wq; a1y += f0.y * wq;
                a1z += f1.x * wq; a1w += f1.y * wq;
            } else {
                a0x += f0.x * wq; a0y += f0.y * wq;
                a0z += f1.x * wq; a0w += f1.y * wq;
            }
        }
    }
    for (; k + 4 <= e; k += 4) {
        int2 p[4];
#pragma unroll
        for (int q = 0; q < 4; q++) p[q] = __ldg(ew + k + q);
        uint2 v[4];
#pragma unroll
        for (int q = 0; q < 4; q++) v[q] = __ldg(hb + (size_t)p[q].x * 32 + lane);
#pragma unroll
        for (int q = 0; q < 4; q++) {
            float wq = __int_as_float(p[q].y);
            float2 f0 = __half22float2(*(const half2*)&v[q].x);
            float2 f1 = __half22float2(*(const half2*)&v[q].y);
            if (q & 1) {
                a1x += f0.x * wq; a1y += f0.y * wq;
                a1z += f1.x * wq; a1w += f1.y * wq;
            } else {
                a0x += f0.x * wq; a0y += f0.y * wq;
                a0z += f1.x * wq; a0w += f1.y * wq;
            }
        }
    }
    for (; k < e; k++) {
        int2 p0 = __ldg(ew + k);
        float w0 = __int_as_float(p0.y);
        uint2 v0 = __ldg(hb + (size_t)p0.x * 32 + lane);
        float2 f0 = __half22float2(*(const half2*)&v0.x);
        float2 f1 = __half22float2(*(const half2*)&v0.y);
        a0x += f0.x * w0; a0y += f0.y * w0;
        a0z += f1.x * w0; a0w += f1.y * w0;
    }

    float4 bv = __ldg((const float4*)bias + lane);
    a0x = fmaxf(a0x + a1x + bv.x, 0.f);
    a0y = fmaxf(a0y + a1y + bv.y, 0.f);
    a0z = fmaxf(a0z + a1z + bv.z, 0.f);
    a0w = fmaxf(a0w + a1w + bv.w, 0.f);

    half2 o0 = __floats2half2_rn(a0x, a0y);
    half2 o1 = __floats2half2_rn(a0z, a0w);
    uint2 ov;
    ov.x = *(const uint32_t*)&o0;
    ov.y = *(const uint32_t*)&o1;
    *((uint2*)out + (size_t)node * 32 + lane) = ov;
}

__global__ void agg64_k(const __half* __restrict__ h, const int2* __restrict__ ew,
                        const int* __restrict__ start, const float* __restrict__ bias,
                        float* __restrict__ out, int n) {
    int node = (blockIdx.x * blockDim.x + threadIdx.x) >> 5;
    int lane = threadIdx.x & 31;
    if (node >= n) return;

    int s = start[node];
    int e = start[node + 1];
    const half2* hb = (const half2*)h;   // row = 32 half2

    float a0x = 0.f, a0y = 0.f, a1x = 0.f, a1y = 0.f;

    int k = s;
    for (; k + 8 <= e; k += 8) {
        int2 p[8];
#pragma unroll
        for (int q = 0; q < 8; q++) p[q] = __ldg(ew + k + q);
        half2 v[8];
#pragma unroll
        for (int q = 0; q < 8; q++) v[q] = __ldg(hb + (size_t)p[q].x * 32 + lane);
#pragma unroll
        for (int q = 0; q < 8; q++) {
            float wq = __int_as_float(p[q].y);
            float2 f = __half22float2(v[q]);
            if (q & 1) { a1x += f.x * wq; a1y += f.y * wq; }
            else       { a0x += f.x * wq; a0y += f.y * wq; }
        }
    }
    for (; k + 4 <= e; k += 4) {
        int2 p[4];
#pragma unroll
        for (int q = 0; q < 4; q++) p[q] = __ldg(ew + k + q);
        half2 v[4];
#pragma unroll
        for (int q = 0; q < 4; q++) v[q] = __ldg(hb + (size_t)p[q].x * 32 + lane);
#pragma unroll
        for (int q = 0; q < 4; q++) {
            float wq = __int_as_float(p[q].y);
            float2 f = __half22float2(v[q]);
            if (q & 1) { a1x += f.x * wq; a1y += f.y * wq; }
            else       { a0x += f.x * wq; a0y += f.y * wq; }
        }
    }
    for (; k < e; k++) {
        int2 p0 = __ldg(ew + k);
        float w0 = __int_as_float(p0.y);
        float2 f = __half22float2(__ldg(hb + (size_t)p0.x * 32 + lane));
        a0x += f.x * w0; a0y += f.y * w0;
    }

    float2 bv = __ldg((const float2*)bias + lane);
    a0x += a1x + bv.x;
    a0y += a1y + bv.y;
    *((float2*)(out + (size_t)node * 64) + lane) = make_float2(a0x, a0y);
}

// ---------------- launch (fork/join: CSC build overlaps prep+gemm1) -------------

extern "C" void kernel_launch(void* const* d_in, const int* in_sizes, int n_in,
                              void* d_out, int out_size) {
    const float* x  = (const float*)d_in[0];
    const int*   ei = (const int*)d_in[1];      // int32 (JAX x64 disabled)
    const float* W1 = (const float*)d_in[2];
    const float* b1 = (const float*)d_in[3];
    const float* W2 = (const float*)d_in[4];
    const float* b2 = (const float*)d_in[5];
    const float* W3 = (const float*)d_in[6];
    const float* b3 = (const float*)d_in[7];
    float* out = (float*)d_out;

    const int N = in_sizes[0] / 128;
    const int E = in_sizes[1] / 2;
    const int* row = ei;
    const int* col = ei + E;

    int *deg, *start, *cursor, *bsums;
    int2* ew;
    float* dinv;
    __half *x16, *h, *act, *w1t, *w2t, *w3t;
    cudaGetSymbolAddress((void**)&deg,    g_deg);
    cudaGetSymbolAddress((void**)&dinv,   g_dinv);
    cudaGetSymbolAddress((void**)&start,  g_start);
    cudaGetSymbolAddress((void**)&cursor, g_cursor);
    cudaGetSymbolAddress((void**)&bsums,  g_bsums);
    cudaGetSymbolAddress((void**)&ew,     g_ew);
    cudaGetSymbolAddress((void**)&x16,    g_x16);
    cudaGetSymbolAddress((void**)&h,      g_h);
    cudaGetSymbolAddress((void**)&act,    g_act);
    cudaGetSymbolAddress((void**)&w1t,    g_w1t);
    cudaGetSymbolAddress((void**)&w2t,    g_w2t);
    cudaGetSymbolAddress((void**)&w3t,    g_w3t);

    // Host-side resources created once (lazy; creation happens on the first,
    // non-captured correctness call — no device memory involved).
    static cudaStream_t s2 = nullptr;
    static cudaEvent_t evF = nullptr, evJ = nullptr;
    if (s2 == nullptr) {
        cudaStreamCreateWithFlags(&s2, cudaStreamNonBlocking);
        cudaEventCreateWithFlags(&evF, cudaEventDisableTiming);
        cudaEventCreateWithFlags(&evJ, cudaEventDisableTiming);
    }

    const int SMEM128 = (64 * XP + 128 * WP) * 2;    // 52224 B
    const int SMEM64  = (128 * XP + 128 * WP) * 2;   // 69632 B
    cudaFuncSetAttribute(gemm_k<128>, cudaFuncAttributeMaxDynamicSharedMemorySize, SMEM128);
    cudaFuncSetAttribute(gemm_k<64>,  cudaFuncAttributeMaxDynamicSharedMemorySize, SMEM64);

    const int TB = 256;
    const int gN    = (N + TB - 1) / TB;
    const int gE    = (E + TB - 1) / TB;
    const int gW    = ((size_t)N * 32 + TB - 1) / TB;  // warp-per-node grid
    const int gG128 = (N + 63) / 64;                   // 64-row tiles
    const int gG64  = (N + 127) / 128;                 // 128-row tiles
    const int gP    = (PREP_TOTAL + TB - 1) / TB;      // fused prep
    const int nb    = (N + SCAN_B - 1) / SCAN_B;       // 98

    // ---- fork ----
    cudaEventRecord(evF, 0);
    cudaStreamWaitEvent(s2, evF, 0);

    // branch B (s2): CSC build
    zero_deg_k<<<gN, TB, 0, s2>>>(deg, N);
    degree_k<<<gE, TB, 0, s2>>>(col, deg, E);
    scan1_dinv_k<<<nb, SCAN_B, 0, s2>>>(deg, start, bsums, dinv, N);
    scan2_k<<<1, MAX_BLOCKS, 0, s2>>>(bsums, nb);
    scan3_cursor_k<<<gN, TB, 0, s2>>>(start, bsums, cursor, N);
    fill_k<<<gE, TB, 0, s2>>>(row, col, dinv, cursor, ew, E);
    cudaEventRecord(evJ, s2);

    // branch A (default stream): prep + gemm1
    prep_k<<<gP, TB>>>(x, W1, W2, W3, w1t, w2t, w3t, (uint2*)x16);
    gemm_k<128><<<gG128, TB, SMEM128>>>(x16, w1t, h, N);

    // ---- join ----
    cudaStreamWaitEvent(0, evJ, 0);

    // ---- layer 1 ----
    agg128_k<<<gW, TB>>>(h, ew, start, b1, act, N);
    // ---- layer 2 ----
    gemm_k<128><<<gG128, TB, SMEM128>>>(act, w2t, h, N);
    agg128_k<<<gW, TB>>>(h, ew, start, b2, act, N);
    // ---- layer 3 ----
    gemm_k<64><<<gG64, TB, SMEM64>>>(act, w3t, h, N);
    agg64_k<<<gW, TB>>>(h, ew, start, b3, out, N);
}